// round 12
// baseline (speedup 1.0000x reference)
#include <cuda_runtime.h>
#include <cuda_bf16.h>
#include <math.h>
#include <float.h>

#define DIM     768
#define B_Q     64
#define N_MAX   500000
#define TOPK    10
#define K_CAND  32

#define BLK_M   256
#define BLK_K   16          // K chunk (smaller -> 4-stage pipeline fits)
#define NSTAGE  4
#define STF     20          // fp32 stage row stride (floats); 80 B, 16B-aligned
#define PADB    24          // bf16 q tile row stride (elements); 48 B

#define NPAD       524288   // padded row count
#define NCTA_PAD   2048     // padded CTA count (>= 1954)

// ---- static device scratch (no cudaMalloc anywhere) ----
__device__ float          g_qn[B_Q * DIM];
__device__ __nv_bfloat16  g_qn_bf[B_Q * DIM];
__device__ unsigned short g_key[(size_t)B_Q * NPAD];            // 64 MB
__device__ unsigned short g_ctamax[B_Q * NCTA_PAD];             // 256 KB (pad stays 0)
__device__ float          g_dummy[64];

// smem layout for gemm (bytes)
#define SM_STAGE   0                                     // 4*256*20*4 = 81920
#define SM_QBF     (NSTAGE * BLK_M * STF * 4)            // 81920
#define SM_TOTAL   (SM_QBF + NSTAGE * 64 * PADB * 2)     // 94208

// ---------------------------------------------------------------------------
__device__ __forceinline__ unsigned short key16(float f) {
    unsigned short us = __bfloat16_as_ushort(__float2bfloat16_rn(f));
    return (us & 0x8000) ? (unsigned short)(~us) : (unsigned short)(us | 0x8000);
}

__device__ __forceinline__ bool better_pk(unsigned ka, int ra, unsigned kb, int rb) {
    return (ka > kb) || (ka == kb && ra < rb);
}
__device__ __forceinline__ bool better_f(float va, int ia, float vb, int ib) {
    return (va > vb) || (va == vb && ia < ib);
}

template <int D>
__device__ __forceinline__ void insK(unsigned k, int r, unsigned* ks, int* rs) {
    if (better_pk(k, r, ks[D - 1], rs[D - 1])) {
        unsigned ck = k; int cr = r;
#pragma unroll
        for (int t = 0; t < D; t++) {
            if (better_pk(ck, cr, ks[t], rs[t])) {
                unsigned tk = ks[t]; int tr = rs[t];
                ks[t] = ck; rs[t] = cr;
                ck = tk; cr = tr;
            }
        }
    }
}

// warp-wide top-32 extraction from per-thread sorted (desc) depth-D lists
template <int D>
__device__ __forceinline__ void warp_top32(unsigned* ks, int* rs,
                                           unsigned* w_key, int* w_row,
                                           int wid, int lane) {
    unsigned curk = ks[0];
    int      curr = rs[0];
    int      pos  = 0;
#pragma unroll 1
    for (int round = 0; round < K_CAND; round++) {
        unsigned bk = curk; int br = curr;
#pragma unroll
        for (int o = 16; o > 0; o >>= 1) {
            unsigned ok  = __shfl_xor_sync(0xffffffff, bk, o);
            int      orr = __shfl_xor_sync(0xffffffff, br, o);
            if (better_pk(ok, orr, bk, br)) { bk = ok; br = orr; }
        }
        if (lane == round) {
            w_key[wid * K_CAND + round] = bk;
            w_row[wid * K_CAND + round] = br;
        }
        if (curk == bk && curr == br) {
            pos++;
#pragma unroll
            for (int t = 1; t < D; t++)
                if (pos == t) { curk = ks[t]; curr = rs[t]; }
            if (pos >= D) { curk = 0u; curr = 0x7fffffff; }
        }
    }
}

// ---------------------------------------------------------------------------
// Kernel 1: L2-normalize queries; write fp32 + bf16 copies.
// ---------------------------------------------------------------------------
__global__ __launch_bounds__(256) void normalize_q(const float* __restrict__ q) {
    __shared__ float red[256];
    const int b = blockIdx.x;
    const float* row = q + (size_t)b * DIM;
    float ss = 0.f;
    for (int i = threadIdx.x; i < DIM; i += 256) {
        float v = row[i];
        ss += v * v;
    }
    red[threadIdx.x] = ss;
    __syncthreads();
    for (int s = 128; s > 0; s >>= 1) {
        if (threadIdx.x < s) red[threadIdx.x] += red[threadIdx.x + s];
        __syncthreads();
    }
    const float inv = 1.0f / fmaxf(sqrtf(red[0]), 1e-12f);
    for (int i = threadIdx.x; i < DIM; i += 256) {
        float v = row[i] * inv;
        g_qn[b * DIM + i]    = v;
        g_qn_bf[b * DIM + i] = __float2bfloat16_rn(v);
    }
}

__global__ void prep1() { if (threadIdx.x < 64) g_dummy[threadIdx.x] = 0.f; }

__device__ __forceinline__ void cp16(void* dst_smem, const void* src) {
    unsigned d = (unsigned)__cvta_generic_to_shared(dst_smem);
    asm volatile("cp.async.cg.shared.global [%0], [%1], 16;" :: "r"(d), "l"(src));
}

// ---------------------------------------------------------------------------
// Kernel 2: bf16 GEMM, 4-stage cp.async pipeline (3 chunks in flight),
//   inline fp32->bf16 fragment conversion, register-fused row norms.
// ---------------------------------------------------------------------------
__global__ __launch_bounds__(256, 2) void gemm_tc(const float* __restrict__ db,
                                                  int N) {
    extern __shared__ char smc[];
    float*          stage = reinterpret_cast<float*>(smc + SM_STAGE);
    __nv_bfloat16*  q_bf  = reinterpret_cast<__nv_bfloat16*>(smc + SM_QBF);

    const int tid  = threadIdx.x;
    const int lane = tid & 31;
    const int warp = tid >> 5;
    const int gid  = lane >> 2;
    const int tig  = lane & 3;
    const int r0   = blockIdx.x * BLK_M;

    float acc[2][8][4];
#pragma unroll
    for (int mt = 0; mt < 2; mt++)
#pragma unroll
        for (int nt = 0; nt < 8; nt++)
#pragma unroll
            for (int k = 0; k < 4; k++) acc[mt][nt][k] = 0.f;

    float nacc[2][2] = {{0.f, 0.f}, {0.f, 0.f}};
    const int NC = DIM / BLK_K;   // 48

    auto issue = [&](int c) {
        const int s  = c & (NSTAGE - 1);
        const int k0 = c * BLK_K;
        float* st = stage + s * BLK_M * STF;
        // db: 256 rows x 64B = 1024 x 16B segments, 4 per thread
#pragma unroll
        for (int i = 0; i < 4; i++) {
            int idx = tid + i * 256;
            int row = idx >> 2;
            int jj  = idx & 3;
            int gr  = r0 + row;
            if (gr >= N) gr = N - 1;
            cp16(st + row * STF + jj * 4, db + (size_t)gr * DIM + k0 + jj * 4);
        }
        // q: 64 rows x 32B = 128 x 16B segments (threads 0..127)
        if (tid < 128) {
            int row = tid >> 1;
            int seg = tid & 1;
            cp16(q_bf + s * 64 * PADB + row * PADB + seg * 8,
                 g_qn_bf + row * DIM + k0 + seg * 8);
        }
        asm volatile("cp.async.commit_group;");
    };

    issue(0); issue(1); issue(2);

    for (int c = 0; c < NC; c++) {
        const int s = c & (NSTAGE - 1);
        if (c <= NC - 3)      asm volatile("cp.async.wait_group 2;");
        else if (c == NC - 2) asm volatile("cp.async.wait_group 1;");
        else                  asm volatile("cp.async.wait_group 0;");
        __syncthreads();                 // buffer (c+3)%4 now reusable by all
        if (c + 3 < NC) issue(c + 3);    // overlaps mma below

        const float*         stg = stage + s * BLK_M * STF;
        const __nv_bfloat16* qb  = q_bf + s * 64 * PADB;

        unsigned a[2][4], b[8][2];
#pragma unroll
        for (int mt = 0; mt < 2; mt++) {
            const float* ap = stg + (warp * 32 + mt * 16 + gid) * STF + 2 * tig;
            float2 p0 = *reinterpret_cast<const float2*>(ap);            // row, k
            float2 p1 = *reinterpret_cast<const float2*>(ap + 8 * STF);  // row+8, k
            float2 p2 = *reinterpret_cast<const float2*>(ap + 8);        // row, k+8
            float2 p3 = *reinterpret_cast<const float2*>(ap + 8 * STF + 8);
            nacc[mt][0] += p0.x * p0.x + p0.y * p0.y + p2.x * p2.x + p2.y * p2.y;
            nacc[mt][1] += p1.x * p1.x + p1.y * p1.y + p3.x * p3.x + p3.y * p3.y;
            __nv_bfloat162 b0 = __float22bfloat162_rn(p0);
            __nv_bfloat162 b1 = __float22bfloat162_rn(p1);
            __nv_bfloat162 b2 = __float22bfloat162_rn(p2);
            __nv_bfloat162 b3 = __float22bfloat162_rn(p3);
            a[mt][0] = *reinterpret_cast<unsigned*>(&b0);
            a[mt][1] = *reinterpret_cast<unsigned*>(&b1);
            a[mt][2] = *reinterpret_cast<unsigned*>(&b2);
            a[mt][3] = *reinterpret_cast<unsigned*>(&b3);
        }
#pragma unroll
        for (int nt = 0; nt < 8; nt++) {
            const __nv_bfloat16* bp = qb + (nt * 8 + gid) * PADB + 2 * tig;
            b[nt][0] = *reinterpret_cast<const unsigned*>(bp);
            b[nt][1] = *reinterpret_cast<const unsigned*>(bp + 8);
        }
#pragma unroll
        for (int mt = 0; mt < 2; mt++)
#pragma unroll
            for (int nt = 0; nt < 8; nt++) {
                float* c4 = acc[mt][nt];
                asm volatile(
                    "mma.sync.aligned.m16n8k16.row.col.f32.bf16.bf16.f32 "
                    "{%0,%1,%2,%3},{%4,%5,%6,%7},{%8,%9},{%0,%1,%2,%3};"
                    : "+f"(c4[0]), "+f"(c4[1]), "+f"(c4[2]), "+f"(c4[3])
                    : "r"(a[mt][0]), "r"(a[mt][1]), "r"(a[mt][2]), "r"(a[mt][3]),
                      "r"(b[nt][0]), "r"(b[nt][1]));
            }
    }

    // row norms: sum across the 4 tig lanes (each k read exactly once)
    float inv_r[2][2];
#pragma unroll
    for (int mt = 0; mt < 2; mt++)
#pragma unroll
        for (int h = 0; h < 2; h++) {
            float v = nacc[mt][h];
            v += __shfl_xor_sync(0xffffffffu, v, 1);
            v += __shfl_xor_sync(0xffffffffu, v, 2);
            inv_r[mt][h] = 1.f / fmaxf(sqrtf(v), 1e-12f);
        }
    __syncthreads();   // all mma frag reads done before key overlay

    // epilogue: pack 16-bit keys into smem overlay (stage region, 32 KB)
    unsigned short* skey = reinterpret_cast<unsigned short*>(smc);  // [64][256]

#pragma unroll
    for (int mt = 0; mt < 2; mt++) {
        const int lr0 = warp * 32 + mt * 16 + gid;
        const float inv0 = inv_r[mt][0];
        const float inv1 = inv_r[mt][1];
        const int gr0 = r0 + lr0;
#pragma unroll
        for (int nt = 0; nt < 8; nt++) {
            const int q = nt * 8 + 2 * tig;
            skey[q * 256 + lr0]           = (gr0 < N)     ? key16(acc[mt][nt][0] * inv0) : (unsigned short)0;
            skey[(q + 1) * 256 + lr0]     = (gr0 < N)     ? key16(acc[mt][nt][1] * inv0) : (unsigned short)0;
            skey[q * 256 + lr0 + 8]       = (gr0 + 8 < N) ? key16(acc[mt][nt][2] * inv1) : (unsigned short)0;
            skey[(q + 1) * 256 + lr0 + 8] = (gr0 + 8 < N) ? key16(acc[mt][nt][3] * inv1) : (unsigned short)0;
        }
    }
    __syncthreads();

    // copy out keys (coalesced) + per-(q, CTA) max via warp reduction
    const uint4* src = reinterpret_cast<const uint4*>(skey);
#pragma unroll
    for (int i = 0; i < 8; i++) {
        int idx = tid + i * 256;
        int q   = idx >> 5;          // all 32 lanes of this warp share q
        int seg = idx & 31;
        uint4 v = src[idx];
        *reinterpret_cast<uint4*>(g_key + (size_t)q * NPAD + r0 + seg * 8) = v;

        unsigned m2 = __vmaxu2(__vmaxu2(v.x, v.y), __vmaxu2(v.z, v.w));
        unsigned m = max(m2 >> 16, m2 & 0xFFFFu);
#pragma unroll
        for (int o = 16; o > 0; o >>= 1)
            m = max(m, __shfl_xor_sync(0xffffffffu, m, o));
        if (lane == 0)
            g_ctamax[q * NCTA_PAD + blockIdx.x] = (unsigned short)m;
    }
}

// ---------------------------------------------------------------------------
// Kernel 3 (fused): per query — top-32 CTAs, gather their keys, top-32 rows,
//   exact fp32 rescore, emit top-10. One block (256 thr) per query.
// ---------------------------------------------------------------------------
__global__ __launch_bounds__(256) void select_finalize(const float* __restrict__ db,
                                                       float* __restrict__ out,
                                                       int N, int Bq, int NCTA) {
    __shared__ unsigned w_key[8 * K_CAND];
    __shared__ int      w_row[8 * K_CAND];
    __shared__ int      selcta[K_CAND];
    __shared__ float    qsh[DIM];
    __shared__ int      cid[K_CAND];
    __shared__ float    cex[K_CAND];

    const int q    = blockIdx.x;
    const int tid  = threadIdx.x;
    const int lane = tid & 31;
    const int wid  = tid >> 5;

    for (int i = tid; i < DIM; i += 256) qsh[i] = g_qn[q * DIM + i];

    // ---- phase 1: top-32 CTAs by (max desc, id asc) ----
    {
        unsigned k8[8]; int r8[8];
#pragma unroll
        for (int t = 0; t < 8; t++) { k8[t] = 0; r8[t] = 0x7fffffff; }
#pragma unroll
        for (int i = 0; i < 8; i++) {
            int idx = tid + i * 256;
            unsigned k = g_ctamax[q * NCTA_PAD + idx];
            insK<8>(k, idx, k8, r8);
        }
        warp_top32<8>(k8, r8, w_key, w_row, wid, lane);
        __syncthreads();
        const unsigned mk = w_key[tid];
        const int      mr = w_row[tid];
        int rank = 0;
        for (int j = 0; j < 8 * K_CAND; j++)
            rank += better_pk(w_key[j], w_row[j], mk, mr) ? 1 : 0;
        if (rank < K_CAND) selcta[rank] = mr;
    }
    __syncthreads();

    // ---- phase 2: gather 32 CTA tiles (8192 keys), top-32 rows ----
    {
        unsigned k6[6]; int r6[6];
#pragma unroll
        for (int t = 0; t < 6; t++) { k6[t] = 0; r6[t] = 0x7fffffff; }
#pragma unroll
        for (int rep = 0; rep < 4; rep++) {
            const int slot = (tid >> 5) + rep * 8;
            const int u4   = tid & 31;
            const int cta  = selcta[slot];
            if (cta >= 0 && cta < NCTA) {
                const int rowb = cta * 256 + u4 * 8;
                uint4 v = *reinterpret_cast<const uint4*>(g_key + (size_t)q * NPAD + rowb);
                unsigned m2 = __vmaxu2(__vmaxu2(v.x, v.y), __vmaxu2(v.z, v.w));
                unsigned hm = max(m2 >> 16, m2 & 0xFFFFu);
                if (hm > k6[5]) {
                    insK<6>(v.x & 0xFFFFu, rowb + 0, k6, r6);
                    insK<6>(v.x >> 16,     rowb + 1, k6, r6);
                    insK<6>(v.y & 0xFFFFu, rowb + 2, k6, r6);
                    insK<6>(v.y >> 16,     rowb + 3, k6, r6);
                    insK<6>(v.z & 0xFFFFu, rowb + 4, k6, r6);
                    insK<6>(v.z >> 16,     rowb + 5, k6, r6);
                    insK<6>(v.w & 0xFFFFu, rowb + 6, k6, r6);
                    insK<6>(v.w >> 16,     rowb + 7, k6, r6);
                }
            }
        }
        __syncthreads();   // selcta reads done before w_key reuse
        warp_top32<6>(k6, r6, w_key, w_row, wid, lane);
        __syncthreads();
        const unsigned mk = w_key[tid];
        const int      mr = w_row[tid];
        int rank = 0;
        for (int j = 0; j < 8 * K_CAND; j++)
            rank += better_pk(w_key[j], w_row[j], mk, mr) ? 1 : 0;
        if (rank < K_CAND) cid[rank] = mr;
    }
    __syncthreads();

    // ---- phase 3: exact fp32 rescore + final top-10 ----
    for (int cc = wid; cc < K_CAND; cc += 8) {
        const int idx = cid[cc];
        float dot = 0.f, nn = 0.f;
        if (idx >= 0 && idx < N) {
            const float* row = db + (size_t)idx * DIM;
            for (int i = lane; i < DIM; i += 32) {
                float d = row[i];
                dot += qsh[i] * d;
                nn  += d * d;
            }
        }
#pragma unroll
        for (int o = 16; o > 0; o >>= 1) {
            dot += __shfl_xor_sync(0xffffffff, dot, o);
            nn  += __shfl_xor_sync(0xffffffff, nn, o);
        }
        if (lane == 0)
            cex[cc] = (idx >= 0 && idx < N)
                          ? dot / fmaxf(sqrtf(nn), 1e-12f)
                          : -FLT_MAX;
    }
    __syncthreads();

    if (tid < K_CAND) {
        const float mv = cex[tid];
        const int   mi = cid[tid];
        int rank = 0;
        for (int j = 0; j < K_CAND; j++)
            rank += better_f(cex[j], cid[j], mv, mi) ? 1 : 0;
        if (rank < TOPK) {
            out[q * TOPK + rank]             = mv;
            out[Bq * TOPK + q * TOPK + rank] = (float)mi;
        }
    }
}

// ---------------------------------------------------------------------------
extern "C" void kernel_launch(void* const* d_in, const int* in_sizes, int n_in,
                              void* d_out, int out_size) {
    const float* query = (const float*)d_in[0];
    const float* db    = (const float*)d_in[1];

    int Bq = in_sizes[0] / DIM;
    int N  = in_sizes[1] / DIM;
    if (Bq > B_Q) Bq = B_Q;
    if (N > N_MAX) N = N_MAX;

    float* out = (float*)d_out;

    static bool attr_set = false;
    if (!attr_set) {
        cudaFuncSetAttribute(gemm_tc, cudaFuncAttributeMaxDynamicSharedMemorySize,
                             SM_TOTAL);
        attr_set = true;
    }

    const int nblk = (N + BLK_M - 1) / BLK_M;   // 1954

    // 4 launches/iter; gemm at position 1 -> launch index 5 (ncu -s 5) = gemm
    normalize_q<<<Bq, 256>>>(query);                      // 0
    gemm_tc<<<nblk, 256, SM_TOTAL>>>(db, N);              // 1
    select_finalize<<<Bq, 256>>>(db, out, N, Bq, nblk);   // 2
    prep1<<<1, 64>>>();                                   // 3
    (void)n_in; (void)out_size;
}

// round 13
// speedup vs baseline: 1.1582x; 1.1582x over previous
#include <cuda_runtime.h>
#include <cuda_bf16.h>
#include <math.h>
#include <float.h>

#define DIM     768
#define B_Q     64
#define N_MAX   500000
#define TOPK    10
#define K_CAND  32

#define BLK_M   256
#define BLK_K   32
#define NSTAGE  3
#define STROW   32          // fp32 stage row stride (floats) = 128 B, swizzled
#define PADB    40          // bf16 q tile row stride (elements)

#define NPAD       524288   // padded row count
#define NCTA_PAD   2048     // padded CTA count (>= 1954)

// ---- static device scratch (no cudaMalloc anywhere) ----
__device__ float          g_qn[B_Q * DIM];
__device__ __nv_bfloat16  g_qn_bf[B_Q * DIM];
__device__ unsigned short g_key[(size_t)B_Q * NPAD];            // 64 MB
__device__ unsigned short g_ctamax[B_Q * NCTA_PAD];             // 256 KB (pad stays 0)
__device__ float          g_dummy[64];

// smem layout for gemm (bytes)
#define SM_STAGE   0                                     // 3*256*32*4 = 98304
#define SM_QBF     (NSTAGE * BLK_M * STROW * 4)          // 98304
#define SM_TOTAL   (SM_QBF + NSTAGE * 64 * PADB * 2)     // 113664

// ---------------------------------------------------------------------------
__device__ __forceinline__ unsigned short key16(float f) {
    unsigned short us = __bfloat16_as_ushort(__float2bfloat16_rn(f));
    return (us & 0x8000) ? (unsigned short)(~us) : (unsigned short)(us | 0x8000);
}

__device__ __forceinline__ bool better_pk(unsigned ka, int ra, unsigned kb, int rb) {
    return (ka > kb) || (ka == kb && ra < rb);
}
__device__ __forceinline__ bool better_f(float va, int ia, float vb, int ib) {
    return (va > vb) || (va == vb && ia < ib);
}

template <int D>
__device__ __forceinline__ void insK(unsigned k, int r, unsigned* ks, int* rs) {
    if (better_pk(k, r, ks[D - 1], rs[D - 1])) {
        unsigned ck = k; int cr = r;
#pragma unroll
        for (int t = 0; t < D; t++) {
            if (better_pk(ck, cr, ks[t], rs[t])) {
                unsigned tk = ks[t]; int tr = rs[t];
                ks[t] = ck; rs[t] = cr;
                ck = tk; cr = tr;
            }
        }
    }
}

// warp-wide top-32 extraction from per-thread sorted (desc) depth-D lists
template <int D>
__device__ __forceinline__ void warp_top32(unsigned* ks, int* rs,
                                           unsigned* w_key, int* w_row,
                                           int wid, int lane) {
    unsigned curk = ks[0];
    int      curr = rs[0];
    int      pos  = 0;
#pragma unroll 1
    for (int round = 0; round < K_CAND; round++) {
        unsigned bk = curk; int br = curr;
#pragma unroll
        for (int o = 16; o > 0; o >>= 1) {
            unsigned ok  = __shfl_xor_sync(0xffffffff, bk, o);
            int      orr = __shfl_xor_sync(0xffffffff, br, o);
            if (better_pk(ok, orr, bk, br)) { bk = ok; br = orr; }
        }
        if (lane == round) {
            w_key[wid * K_CAND + round] = bk;
            w_row[wid * K_CAND + round] = br;
        }
        if (curk == bk && curr == br) {
            pos++;
#pragma unroll
            for (int t = 1; t < D; t++)
                if (pos == t) { curk = ks[t]; curr = rs[t]; }
            if (pos >= D) { curk = 0u; curr = 0x7fffffff; }
        }
    }
}

// ---------------------------------------------------------------------------
// Kernel 1: L2-normalize queries; write fp32 + bf16 copies.
// ---------------------------------------------------------------------------
__global__ __launch_bounds__(256) void normalize_q(const float* __restrict__ q) {
    __shared__ float red[256];
    const int b = blockIdx.x;
    const float* row = q + (size_t)b * DIM;
    float ss = 0.f;
    for (int i = threadIdx.x; i < DIM; i += 256) {
        float v = row[i];
        ss += v * v;
    }
    red[threadIdx.x] = ss;
    __syncthreads();
    for (int s = 128; s > 0; s >>= 1) {
        if (threadIdx.x < s) red[threadIdx.x] += red[threadIdx.x + s];
        __syncthreads();
    }
    const float inv = 1.0f / fmaxf(sqrtf(red[0]), 1e-12f);
    for (int i = threadIdx.x; i < DIM; i += 256) {
        float v = row[i] * inv;
        g_qn[b * DIM + i]    = v;
        g_qn_bf[b * DIM + i] = __float2bfloat16_rn(v);
    }
}

__global__ void prep1() { if (threadIdx.x < 64) g_dummy[threadIdx.x] = 0.f; }
__global__ void prep2() { if (threadIdx.x < 64) g_dummy[threadIdx.x] = 1.f; }

__device__ __forceinline__ void cp16(void* dst_smem, const void* src) {
    unsigned d = (unsigned)__cvta_generic_to_shared(dst_smem);
    asm volatile("cp.async.cg.shared.global [%0], [%1], 16;" :: "r"(d), "l"(src));
}

// ---------------------------------------------------------------------------
// Kernel 2: bf16 GEMM, 3-stage cp.async pipeline (2 chunks in flight/CTA),
//   swizzled pad-free fp32 stage, inline fp32->bf16 fragment conversion,
//   register-fused row norms, key epilogue + per-CTA max.
// ---------------------------------------------------------------------------
__global__ __launch_bounds__(256, 2) void gemm_tc(const float* __restrict__ db,
                                                  int N) {
    extern __shared__ char smc[];
    float*          stage = reinterpret_cast<float*>(smc + SM_STAGE);
    __nv_bfloat16*  q_bf  = reinterpret_cast<__nv_bfloat16*>(smc + SM_QBF);

    const int tid  = threadIdx.x;
    const int lane = tid & 31;
    const int warp = tid >> 5;
    const int gid  = lane >> 2;
    const int tig  = lane & 3;
    const int r0   = blockIdx.x * BLK_M;
    const int vx   = (gid & 3) << 1;     // frag-read swizzle (row&3 == gid&3)

    float acc[2][8][4];
#pragma unroll
    for (int mt = 0; mt < 2; mt++)
#pragma unroll
        for (int nt = 0; nt < 8; nt++)
#pragma unroll
            for (int k = 0; k < 4; k++) acc[mt][nt][k] = 0.f;

    float nacc[2][2] = {{0.f, 0.f}, {0.f, 0.f}};
    const int NC = DIM / BLK_K;   // 24

    auto issue = [&](int c, int s) {
        const int k0 = c * BLK_K;
        float* st = stage + s * BLK_M * STROW;
        // db: 256 rows x 128B = 2048 x 16B segments, 8 per thread (swizzled)
#pragma unroll
        for (int i = 0; i < 8; i++) {
            int idx = tid + i * 256;
            int row = idx >> 3;
            int jj  = idx & 7;
            int gr  = r0 + row;
            if (gr >= N) gr = N - 1;
            int sj = jj ^ ((row & 3) << 1);
            cp16(st + row * STROW + sj * 4, db + (size_t)gr * DIM + k0 + jj * 4);
        }
        // q: 64 rows x 64B = 256 x 16B segments, 1 per thread
        {
            int row = tid >> 2;
            int seg = tid & 3;
            cp16(q_bf + s * 64 * PADB + row * PADB + seg * 8,
                 g_qn_bf + row * DIM + k0 + seg * 8);
        }
        asm volatile("cp.async.commit_group;");
    };

    issue(0, 0);
    issue(1, 1);

    int s = 0;
    for (int c = 0; c < NC; c++) {
        if (c < NC - 1) asm volatile("cp.async.wait_group 1;");
        else            asm volatile("cp.async.wait_group 0;");
        __syncthreads();                 // stage s ready; stage (s+2)%3 free
        if (c + 2 < NC) {
            int sp = s + 2; if (sp >= NSTAGE) sp -= NSTAGE;
            issue(c + 2, sp);            // overlaps mma below
        }

        const float*         stg = stage + s * BLK_M * STROW;
        const __nv_bfloat16* qb  = q_bf + s * 64 * PADB;

#pragma unroll
        for (int ks = 0; ks < BLK_K; ks += 16) {
            const int f0 = ks + 2 * tig;
            const int f2 = f0 + 8;
            const int o0 = ((((f0 >> 2) ^ vx) << 2) | (f0 & 3));
            const int o2 = ((((f2 >> 2) ^ vx) << 2) | (f2 & 3));

            unsigned a[2][4], b[8][2];
#pragma unroll
            for (int mt = 0; mt < 2; mt++) {
                const float* rp = stg + (warp * 32 + mt * 16 + gid) * STROW;
                float2 p0 = *reinterpret_cast<const float2*>(rp + o0);
                float2 p1 = *reinterpret_cast<const float2*>(rp + 8 * STROW + o0);
                float2 p2 = *reinterpret_cast<const float2*>(rp + o2);
                float2 p3 = *reinterpret_cast<const float2*>(rp + 8 * STROW + o2);
                nacc[mt][0] += p0.x * p0.x + p0.y * p0.y + p2.x * p2.x + p2.y * p2.y;
                nacc[mt][1] += p1.x * p1.x + p1.y * p1.y + p3.x * p3.x + p3.y * p3.y;
                __nv_bfloat162 b0 = __float22bfloat162_rn(p0);
                __nv_bfloat162 b1 = __float22bfloat162_rn(p1);
                __nv_bfloat162 b2 = __float22bfloat162_rn(p2);
                __nv_bfloat162 b3 = __float22bfloat162_rn(p3);
                a[mt][0] = *reinterpret_cast<unsigned*>(&b0);
                a[mt][1] = *reinterpret_cast<unsigned*>(&b1);
                a[mt][2] = *reinterpret_cast<unsigned*>(&b2);
                a[mt][3] = *reinterpret_cast<unsigned*>(&b3);
            }
#pragma unroll
            for (int nt = 0; nt < 8; nt++) {
                const __nv_bfloat16* bp = qb + (nt * 8 + gid) * PADB + ks + 2 * tig;
                b[nt][0] = *reinterpret_cast<const unsigned*>(bp);
                b[nt][1] = *reinterpret_cast<const unsigned*>(bp + 8);
            }
#pragma unroll
            for (int mt = 0; mt < 2; mt++)
#pragma unroll
                for (int nt = 0; nt < 8; nt++) {
                    float* c4 = acc[mt][nt];
                    asm volatile(
                        "mma.sync.aligned.m16n8k16.row.col.f32.bf16.bf16.f32 "
                        "{%0,%1,%2,%3},{%4,%5,%6,%7},{%8,%9},{%0,%1,%2,%3};"
                        : "+f"(c4[0]), "+f"(c4[1]), "+f"(c4[2]), "+f"(c4[3])
                        : "r"(a[mt][0]), "r"(a[mt][1]), "r"(a[mt][2]), "r"(a[mt][3]),
                          "r"(b[nt][0]), "r"(b[nt][1]));
                }
        }
        s++; if (s >= NSTAGE) s = 0;
    }

    // row norms: sum across the 4 tig lanes (each k read exactly once)
    float inv_r[2][2];
#pragma unroll
    for (int mt = 0; mt < 2; mt++)
#pragma unroll
        for (int h = 0; h < 2; h++) {
            float v = nacc[mt][h];
            v += __shfl_xor_sync(0xffffffffu, v, 1);
            v += __shfl_xor_sync(0xffffffffu, v, 2);
            inv_r[mt][h] = 1.f / fmaxf(sqrtf(v), 1e-12f);
        }
    __syncthreads();   // all frag reads done before key overlay

    // epilogue: pack 16-bit keys into smem overlay (stage region, 32 KB)
    unsigned short* skey = reinterpret_cast<unsigned short*>(smc);  // [64][256]

#pragma unroll
    for (int mt = 0; mt < 2; mt++) {
        const int lr0 = warp * 32 + mt * 16 + gid;
        const float inv0 = inv_r[mt][0];
        const float inv1 = inv_r[mt][1];
        const int gr0 = r0 + lr0;
#pragma unroll
        for (int nt = 0; nt < 8; nt++) {
            const int q = nt * 8 + 2 * tig;
            skey[q * 256 + lr0]           = (gr0 < N)     ? key16(acc[mt][nt][0] * inv0) : (unsigned short)0;
            skey[(q + 1) * 256 + lr0]     = (gr0 < N)     ? key16(acc[mt][nt][1] * inv0) : (unsigned short)0;
            skey[q * 256 + lr0 + 8]       = (gr0 + 8 < N) ? key16(acc[mt][nt][2] * inv1) : (unsigned short)0;
            skey[(q + 1) * 256 + lr0 + 8] = (gr0 + 8 < N) ? key16(acc[mt][nt][3] * inv1) : (unsigned short)0;
        }
    }
    __syncthreads();

    // copy out keys (coalesced) + per-(q, CTA) max via warp reduction
    const uint4* src = reinterpret_cast<const uint4*>(skey);
#pragma unroll
    for (int i = 0; i < 8; i++) {
        int idx = tid + i * 256;
        int q   = idx >> 5;          // all 32 lanes of this warp share q
        int seg = idx & 31;
        uint4 v = src[idx];
        *reinterpret_cast<uint4*>(g_key + (size_t)q * NPAD + r0 + seg * 8) = v;

        unsigned m2 = __vmaxu2(__vmaxu2(v.x, v.y), __vmaxu2(v.z, v.w));
        unsigned m = max(m2 >> 16, m2 & 0xFFFFu);
#pragma unroll
        for (int o = 16; o > 0; o >>= 1)
            m = max(m, __shfl_xor_sync(0xffffffffu, m, o));
        if (lane == 0)
            g_ctamax[q * NCTA_PAD + blockIdx.x] = (unsigned short)m;
    }
}

// ---------------------------------------------------------------------------
// Kernel 3 (fused): per query — top-32 CTAs, gather their keys, top-32 rows,
//   exact fp32 rescore, emit top-10. One block (256 thr) per query.
// ---------------------------------------------------------------------------
__global__ __launch_bounds__(256) void select_finalize(const float* __restrict__ db,
                                                       float* __restrict__ out,
                                                       int N, int Bq, int NCTA) {
    __shared__ unsigned w_key[8 * K_CAND];
    __shared__ int      w_row[8 * K_CAND];
    __shared__ int      selcta[K_CAND];
    __shared__ float    qsh[DIM];
    __shared__ int      cid[K_CAND];
    __shared__ float    cex[K_CAND];

    const int q    = blockIdx.x;
    const int tid  = threadIdx.x;
    const int lane = tid & 31;
    const int wid  = tid >> 5;

    for (int i = tid; i < DIM; i += 256) qsh[i] = g_qn[q * DIM + i];

    // ---- phase 1: top-32 CTAs by (max desc, id asc) ----
    {
        unsigned k8[8]; int r8[8];
#pragma unroll
        for (int t = 0; t < 8; t++) { k8[t] = 0; r8[t] = 0x7fffffff; }
#pragma unroll
        for (int i = 0; i < 8; i++) {
            int idx = tid + i * 256;
            unsigned k = g_ctamax[q * NCTA_PAD + idx];
            insK<8>(k, idx, k8, r8);
        }
        warp_top32<8>(k8, r8, w_key, w_row, wid, lane);
        __syncthreads();
        const unsigned mk = w_key[tid];
        const int      mr = w_row[tid];
        int rank = 0;
        for (int j = 0; j < 8 * K_CAND; j++)
            rank += better_pk(w_key[j], w_row[j], mk, mr) ? 1 : 0;
        if (rank < K_CAND) selcta[rank] = mr;
    }
    __syncthreads();

    // ---- phase 2: gather 32 CTA tiles (8192 keys), top-32 rows ----
    {
        unsigned k6[6]; int r6[6];
#pragma unroll
        for (int t = 0; t < 6; t++) { k6[t] = 0; r6[t] = 0x7fffffff; }
#pragma unroll
        for (int rep = 0; rep < 4; rep++) {
            const int slot = (tid >> 5) + rep * 8;
            const int u4   = tid & 31;
            const int cta  = selcta[slot];
            if (cta >= 0 && cta < NCTA) {
                const int rowb = cta * 256 + u4 * 8;
                uint4 v = *reinterpret_cast<const uint4*>(g_key + (size_t)q * NPAD + rowb);
                unsigned m2 = __vmaxu2(__vmaxu2(v.x, v.y), __vmaxu2(v.z, v.w));
                unsigned hm = max(m2 >> 16, m2 & 0xFFFFu);
                if (hm > k6[5]) {
                    insK<6>(v.x & 0xFFFFu, rowb + 0, k6, r6);
                    insK<6>(v.x >> 16,     rowb + 1, k6, r6);
                    insK<6>(v.y & 0xFFFFu, rowb + 2, k6, r6);
                    insK<6>(v.y >> 16,     rowb + 3, k6, r6);
                    insK<6>(v.z & 0xFFFFu, rowb + 4, k6, r6);
                    insK<6>(v.z >> 16,     rowb + 5, k6, r6);
                    insK<6>(v.w & 0xFFFFu, rowb + 6, k6, r6);
                    insK<6>(v.w >> 16,     rowb + 7, k6, r6);
                }
            }
        }
        __syncthreads();   // selcta reads done before w_key reuse
        warp_top32<6>(k6, r6, w_key, w_row, wid, lane);
        __syncthreads();
        const unsigned mk = w_key[tid];
        const int      mr = w_row[tid];
        int rank = 0;
        for (int j = 0; j < 8 * K_CAND; j++)
            rank += better_pk(w_key[j], w_row[j], mk, mr) ? 1 : 0;
        if (rank < K_CAND) cid[rank] = mr;
    }
    __syncthreads();

    // ---- phase 3: exact fp32 rescore + final top-10 ----
    for (int cc = wid; cc < K_CAND; cc += 8) {
        const int idx = cid[cc];
        float dot = 0.f, nn = 0.f;
        if (idx >= 0 && idx < N) {
            const float* row = db + (size_t)idx * DIM;
            for (int i = lane; i < DIM; i += 32) {
                float d = row[i];
                dot += qsh[i] * d;
                nn  += d * d;
            }
        }
#pragma unroll
        for (int o = 16; o > 0; o >>= 1) {
            dot += __shfl_xor_sync(0xffffffff, dot, o);
            nn  += __shfl_xor_sync(0xffffffff, nn, o);
        }
        if (lane == 0)
            cex[cc] = (idx >= 0 && idx < N)
                          ? dot / fmaxf(sqrtf(nn), 1e-12f)
                          : -FLT_MAX;
    }
    __syncthreads();

    if (tid < K_CAND) {
        const float mv = cex[tid];
        const int   mi = cid[tid];
        int rank = 0;
        for (int j = 0; j < K_CAND; j++)
            rank += better_f(cex[j], cid[j], mv, mi) ? 1 : 0;
        if (rank < TOPK) {
            out[q * TOPK + rank]             = mv;
            out[Bq * TOPK + q * TOPK + rank] = (float)mi;
        }
    }
}

// ---------------------------------------------------------------------------
extern "C" void kernel_launch(void* const* d_in, const int* in_sizes, int n_in,
                              void* d_out, int out_size) {
    const float* query = (const float*)d_in[0];
    const float* db    = (const float*)d_in[1];

    int Bq = in_sizes[0] / DIM;
    int N  = in_sizes[1] / DIM;
    if (Bq > B_Q) Bq = B_Q;
    if (N > N_MAX) N = N_MAX;

    float* out = (float*)d_out;

    static bool attr_set = false;
    if (!attr_set) {
        cudaFuncSetAttribute(gemm_tc, cudaFuncAttributeMaxDynamicSharedMemorySize,
                             SM_TOTAL);
        attr_set = true;
    }

    const int nblk = (N + BLK_M - 1) / BLK_M;   // 1954

    // ncu captures launch index 3 (mod len) -> gemm_tc sits at index 3.
    normalize_q<<<Bq, 256>>>(query);                      // 0
    prep1<<<1, 64>>>();                                   // 1
    prep2<<<1, 64>>>();                                   // 2
    gemm_tc<<<nblk, 256, SM_TOTAL>>>(db, N);              // 3  (profiled)
    select_finalize<<<Bq, 256>>>(db, out, N, Bq, nblk);   // 4
    (void)n_in; (void)out_size;
}

// round 14
// speedup vs baseline: 1.1804x; 1.0191x over previous
#include <cuda_runtime.h>
#include <cuda_bf16.h>
#include <math.h>
#include <float.h>

#define DIM     768
#define B_Q     64
#define N_MAX   500000
#define TOPK    10
#define K_CAND  32

#define BLK_M   256
#define BLK_K   32
#define NSTAGE  3
#define STROW   32          // fp32 stage row stride (floats) = 128 B, swizzled
#define PADB    40          // bf16 q tile row stride (elements)

#define NPAD       524288   // padded row count
#define NCTA_PAD   2048     // padded CTA count (>= 1954)

// ---- static device scratch (no cudaMalloc anywhere) ----
__device__ float          g_qn[B_Q * DIM];
__device__ __nv_bfloat16  g_qn_bf[B_Q * DIM];
__device__ unsigned short g_key[(size_t)B_Q * NPAD];            // 64 MB
__device__ unsigned short g_ctamax[B_Q * NCTA_PAD];             // 256 KB (pad stays 0)

// smem layout for gemm (bytes)
#define SM_STAGE   0                                     // 3*256*32*4 = 98304
#define SM_QBF     (NSTAGE * BLK_M * STROW * 4)          // 98304
#define SM_TOTAL   (SM_QBF + NSTAGE * 64 * PADB * 2)     // 113664

// ---------------------------------------------------------------------------
__device__ __forceinline__ unsigned short key16(float f) {
    unsigned short us = __bfloat16_as_ushort(__float2bfloat16_rn(f));
    return (us & 0x8000) ? (unsigned short)(~us) : (unsigned short)(us | 0x8000);
}

__device__ __forceinline__ bool better_pk(unsigned ka, int ra, unsigned kb, int rb) {
    return (ka > kb) || (ka == kb && ra < rb);
}
__device__ __forceinline__ bool better_f(float va, int ia, float vb, int ib) {
    return (va > vb) || (va == vb && ia < ib);
}

template <int D>
__device__ __forceinline__ void insK(unsigned k, int r, unsigned* ks, int* rs) {
    if (better_pk(k, r, ks[D - 1], rs[D - 1])) {
        unsigned ck = k; int cr = r;
#pragma unroll
        for (int t = 0; t < D; t++) {
            if (better_pk(ck, cr, ks[t], rs[t])) {
                unsigned tk = ks[t]; int tr = rs[t];
                ks[t] = ck; rs[t] = cr;
                ck = tk; cr = tr;
            }
        }
    }
}

// warp-wide top-32 extraction from per-thread sorted (desc) depth-D lists
template <int D>
__device__ __forceinline__ void warp_top32(unsigned* ks, int* rs,
                                           unsigned* w_key, int* w_row,
                                           int wid, int lane) {
    unsigned curk = ks[0];
    int      curr = rs[0];
    int      pos  = 0;
#pragma unroll 1
    for (int round = 0; round < K_CAND; round++) {
        unsigned bk = curk; int br = curr;
#pragma unroll
        for (int o = 16; o > 0; o >>= 1) {
            unsigned ok  = __shfl_xor_sync(0xffffffff, bk, o);
            int      orr = __shfl_xor_sync(0xffffffff, br, o);
            if (better_pk(ok, orr, bk, br)) { bk = ok; br = orr; }
        }
        if (lane == round) {
            w_key[wid * K_CAND + round] = bk;
            w_row[wid * K_CAND + round] = br;
        }
        if (curk == bk && curr == br) {
            pos++;
#pragma unroll
            for (int t = 1; t < D; t++)
                if (pos == t) { curk = ks[t]; curr = rs[t]; }
            if (pos >= D) { curk = 0u; curr = 0x7fffffff; }
        }
    }
}

// ---------------------------------------------------------------------------
// Kernel 1: L2-normalize queries; write fp32 + bf16 copies.
// ---------------------------------------------------------------------------
__global__ __launch_bounds__(256) void normalize_q(const float* __restrict__ q) {
    __shared__ float red[256];
    const int b = blockIdx.x;
    const float* row = q + (size_t)b * DIM;
    float ss = 0.f;
    for (int i = threadIdx.x; i < DIM; i += 256) {
        float v = row[i];
        ss += v * v;
    }
    red[threadIdx.x] = ss;
    __syncthreads();
    for (int s = 128; s > 0; s >>= 1) {
        if (threadIdx.x < s) red[threadIdx.x] += red[threadIdx.x + s];
        __syncthreads();
    }
    const float inv = 1.0f / fmaxf(sqrtf(red[0]), 1e-12f);
    for (int i = threadIdx.x; i < DIM; i += 256) {
        float v = row[i] * inv;
        g_qn[b * DIM + i]    = v;
        g_qn_bf[b * DIM + i] = __float2bfloat16_rn(v);
    }
}

__device__ __forceinline__ void cp16(void* dst_smem, const void* src) {
    unsigned d = (unsigned)__cvta_generic_to_shared(dst_smem);
    asm volatile("cp.async.cg.shared.global [%0], [%1], 16;" :: "r"(d), "l"(src));
}

// ---------------------------------------------------------------------------
// Kernel 2: bf16 GEMM, 3-stage cp.async pipeline (2 chunks in flight/CTA),
//   swizzled pad-free fp32 stage, inline fp32->bf16 fragment conversion,
//   register-fused row norms, key epilogue + per-CTA max. (R13 winner, as-is)
// ---------------------------------------------------------------------------
__global__ __launch_bounds__(256, 2) void gemm_tc(const float* __restrict__ db,
                                                  int N) {
    extern __shared__ char smc[];
    float*          stage = reinterpret_cast<float*>(smc + SM_STAGE);
    __nv_bfloat16*  q_bf  = reinterpret_cast<__nv_bfloat16*>(smc + SM_QBF);

    const int tid  = threadIdx.x;
    const int lane = tid & 31;
    const int warp = tid >> 5;
    const int gid  = lane >> 2;
    const int tig  = lane & 3;
    const int r0   = blockIdx.x * BLK_M;
    const int vx   = (gid & 3) << 1;     // frag-read swizzle (row&3 == gid&3)

    float acc[2][8][4];
#pragma unroll
    for (int mt = 0; mt < 2; mt++)
#pragma unroll
        for (int nt = 0; nt < 8; nt++)
#pragma unroll
            for (int k = 0; k < 4; k++) acc[mt][nt][k] = 0.f;

    float nacc[2][2] = {{0.f, 0.f}, {0.f, 0.f}};
    const int NC = DIM / BLK_K;   // 24

    auto issue = [&](int c, int s) {
        const int k0 = c * BLK_K;
        float* st = stage + s * BLK_M * STROW;
#pragma unroll
        for (int i = 0; i < 8; i++) {
            int idx = tid + i * 256;
            int row = idx >> 3;
            int jj  = idx & 7;
            int gr  = r0 + row;
            if (gr >= N) gr = N - 1;
            int sj = jj ^ ((row & 3) << 1);
            cp16(st + row * STROW + sj * 4, db + (size_t)gr * DIM + k0 + jj * 4);
        }
        {
            int row = tid >> 2;
            int seg = tid & 3;
            cp16(q_bf + s * 64 * PADB + row * PADB + seg * 8,
                 g_qn_bf + row * DIM + k0 + seg * 8);
        }
        asm volatile("cp.async.commit_group;");
    };

    issue(0, 0);
    issue(1, 1);

    int s = 0;
    for (int c = 0; c < NC; c++) {
        if (c < NC - 1) asm volatile("cp.async.wait_group 1;");
        else            asm volatile("cp.async.wait_group 0;");
        __syncthreads();                 // stage s ready; stage (s+2)%3 free
        if (c + 2 < NC) {
            int sp = s + 2; if (sp >= NSTAGE) sp -= NSTAGE;
            issue(c + 2, sp);            // overlaps mma below
        }

        const float*         stg = stage + s * BLK_M * STROW;
        const __nv_bfloat16* qb  = q_bf + s * 64 * PADB;

#pragma unroll
        for (int ks = 0; ks < BLK_K; ks += 16) {
            const int f0 = ks + 2 * tig;
            const int f2 = f0 + 8;
            const int o0 = ((((f0 >> 2) ^ vx) << 2) | (f0 & 3));
            const int o2 = ((((f2 >> 2) ^ vx) << 2) | (f2 & 3));

            unsigned a[2][4], b[8][2];
#pragma unroll
            for (int mt = 0; mt < 2; mt++) {
                const float* rp = stg + (warp * 32 + mt * 16 + gid) * STROW;
                float2 p0 = *reinterpret_cast<const float2*>(rp + o0);
                float2 p1 = *reinterpret_cast<const float2*>(rp + 8 * STROW + o0);
                float2 p2 = *reinterpret_cast<const float2*>(rp + o2);
                float2 p3 = *reinterpret_cast<const float2*>(rp + 8 * STROW + o2);
                nacc[mt][0] += p0.x * p0.x + p0.y * p0.y + p2.x * p2.x + p2.y * p2.y;
                nacc[mt][1] += p1.x * p1.x + p1.y * p1.y + p3.x * p3.x + p3.y * p3.y;
                __nv_bfloat162 b0 = __float22bfloat162_rn(p0);
                __nv_bfloat162 b1 = __float22bfloat162_rn(p1);
                __nv_bfloat162 b2 = __float22bfloat162_rn(p2);
                __nv_bfloat162 b3 = __float22bfloat162_rn(p3);
                a[mt][0] = *reinterpret_cast<unsigned*>(&b0);
                a[mt][1] = *reinterpret_cast<unsigned*>(&b1);
                a[mt][2] = *reinterpret_cast<unsigned*>(&b2);
                a[mt][3] = *reinterpret_cast<unsigned*>(&b3);
            }
#pragma unroll
            for (int nt = 0; nt < 8; nt++) {
                const __nv_bfloat16* bp = qb + (nt * 8 + gid) * PADB + ks + 2 * tig;
                b[nt][0] = *reinterpret_cast<const unsigned*>(bp);
                b[nt][1] = *reinterpret_cast<const unsigned*>(bp + 8);
            }
#pragma unroll
            for (int mt = 0; mt < 2; mt++)
#pragma unroll
                for (int nt = 0; nt < 8; nt++) {
                    float* c4 = acc[mt][nt];
                    asm volatile(
                        "mma.sync.aligned.m16n8k16.row.col.f32.bf16.bf16.f32 "
                        "{%0,%1,%2,%3},{%4,%5,%6,%7},{%8,%9},{%0,%1,%2,%3};"
                        : "+f"(c4[0]), "+f"(c4[1]), "+f"(c4[2]), "+f"(c4[3])
                        : "r"(a[mt][0]), "r"(a[mt][1]), "r"(a[mt][2]), "r"(a[mt][3]),
                          "r"(b[nt][0]), "r"(b[nt][1]));
                }
        }
        s++; if (s >= NSTAGE) s = 0;
    }

    // row norms: sum across the 4 tig lanes (each k read exactly once)
    float inv_r[2][2];
#pragma unroll
    for (int mt = 0; mt < 2; mt++)
#pragma unroll
        for (int h = 0; h < 2; h++) {
            float v = nacc[mt][h];
            v += __shfl_xor_sync(0xffffffffu, v, 1);
            v += __shfl_xor_sync(0xffffffffu, v, 2);
            inv_r[mt][h] = 1.f / fmaxf(sqrtf(v), 1e-12f);
        }
    __syncthreads();   // all frag reads done before key overlay

    // epilogue: pack 16-bit keys into smem overlay (stage region, 32 KB)
    unsigned short* skey = reinterpret_cast<unsigned short*>(smc);  // [64][256]

#pragma unroll
    for (int mt = 0; mt < 2; mt++) {
        const int lr0 = warp * 32 + mt * 16 + gid;
        const float inv0 = inv_r[mt][0];
        const float inv1 = inv_r[mt][1];
        const int gr0 = r0 + lr0;
#pragma unroll
        for (int nt = 0; nt < 8; nt++) {
            const int q = nt * 8 + 2 * tig;
            skey[q * 256 + lr0]           = (gr0 < N)     ? key16(acc[mt][nt][0] * inv0) : (unsigned short)0;
            skey[(q + 1) * 256 + lr0]     = (gr0 < N)     ? key16(acc[mt][nt][1] * inv0) : (unsigned short)0;
            skey[q * 256 + lr0 + 8]       = (gr0 + 8 < N) ? key16(acc[mt][nt][2] * inv1) : (unsigned short)0;
            skey[(q + 1) * 256 + lr0 + 8] = (gr0 + 8 < N) ? key16(acc[mt][nt][3] * inv1) : (unsigned short)0;
        }
    }
    __syncthreads();

    // copy out keys (coalesced) + per-(q, CTA) max via warp reduction
    const uint4* src = reinterpret_cast<const uint4*>(skey);
#pragma unroll
    for (int i = 0; i < 8; i++) {
        int idx = tid + i * 256;
        int q   = idx >> 5;          // all 32 lanes of this warp share q
        int seg = idx & 31;
        uint4 v = src[idx];
        *reinterpret_cast<uint4*>(g_key + (size_t)q * NPAD + r0 + seg * 8) = v;

        unsigned m2 = __vmaxu2(__vmaxu2(v.x, v.y), __vmaxu2(v.z, v.w));
        unsigned m = max(m2 >> 16, m2 & 0xFFFFu);
#pragma unroll
        for (int o = 16; o > 0; o >>= 1)
            m = max(m, __shfl_xor_sync(0xffffffffu, m, o));
        if (lane == 0)
            g_ctamax[q * NCTA_PAD + blockIdx.x] = (unsigned short)m;
    }
}

// ---------------------------------------------------------------------------
// Kernel 3 (fused): per query — top-32 CTAs, gather their keys, top-32 rows,
//   exact fp32 rescore, emit top-10. One block (256 thr) per query.
// ---------------------------------------------------------------------------
__global__ __launch_bounds__(256) void select_finalize(const float* __restrict__ db,
                                                       float* __restrict__ out,
                                                       int N, int Bq, int NCTA) {
    __shared__ unsigned w_key[8 * K_CAND];
    __shared__ int      w_row[8 * K_CAND];
    __shared__ int      selcta[K_CAND];
    __shared__ float    qsh[DIM];
    __shared__ int      cid[K_CAND];
    __shared__ float    cex[K_CAND];

    const int q    = blockIdx.x;
    const int tid  = threadIdx.x;
    const int lane = tid & 31;
    const int wid  = tid >> 5;

    for (int i = tid; i < DIM; i += 256) qsh[i] = g_qn[q * DIM + i];

    // ---- phase 1: top-32 CTAs by (max desc, id asc); vectorized uint4 load ----
    {
        unsigned k8[8]; int r8[8];
#pragma unroll
        for (int t = 0; t < 8; t++) { k8[t] = 0; r8[t] = 0x7fffffff; }
        // 2048 shorts = 256 uint4; thread tid owns keys [tid*8, tid*8+8)
        uint4 v = *reinterpret_cast<const uint4*>(g_ctamax + q * NCTA_PAD + tid * 8);
        const int base = tid * 8;
        insK<8>(v.x & 0xFFFFu, base + 0, k8, r8);
        insK<8>(v.x >> 16,     base + 1, k8, r8);
        insK<8>(v.y & 0xFFFFu, base + 2, k8, r8);
        insK<8>(v.y >> 16,     base + 3, k8, r8);
        insK<8>(v.z & 0xFFFFu, base + 4, k8, r8);
        insK<8>(v.z >> 16,     base + 5, k8, r8);
        insK<8>(v.w & 0xFFFFu, base + 6, k8, r8);
        insK<8>(v.w >> 16,     base + 7, k8, r8);

        warp_top32<8>(k8, r8, w_key, w_row, wid, lane);
        __syncthreads();
        const unsigned mk = w_key[tid];
        const int      mr = w_row[tid];
        int rank = 0;
        for (int j = 0; j < 8 * K_CAND; j++)
            rank += better_pk(w_key[j], w_row[j], mk, mr) ? 1 : 0;
        if (rank < K_CAND) selcta[rank] = mr;
    }
    __syncthreads();

    // ---- phase 2: gather 32 CTA tiles (8192 keys), top-32 rows ----
    {
        unsigned k6[6]; int r6[6];
#pragma unroll
        for (int t = 0; t < 6; t++) { k6[t] = 0; r6[t] = 0x7fffffff; }
#pragma unroll
        for (int rep = 0; rep < 4; rep++) {
            const int slot = (tid >> 5) + rep * 8;
            const int u4   = tid & 31;
            const int cta  = selcta[slot];
            if (cta >= 0 && cta < NCTA) {
                const int rowb = cta * 256 + u4 * 8;
                uint4 v = *reinterpret_cast<const uint4*>(g_key + (size_t)q * NPAD + rowb);
                unsigned m2 = __vmaxu2(__vmaxu2(v.x, v.y), __vmaxu2(v.z, v.w));
                unsigned hm = max(m2 >> 16, m2 & 0xFFFFu);
                if (hm > k6[5]) {
                    insK<6>(v.x & 0xFFFFu, rowb + 0, k6, r6);
                    insK<6>(v.x >> 16,     rowb + 1, k6, r6);
                    insK<6>(v.y & 0xFFFFu, rowb + 2, k6, r6);
                    insK<6>(v.y >> 16,     rowb + 3, k6, r6);
                    insK<6>(v.z & 0xFFFFu, rowb + 4, k6, r6);
                    insK<6>(v.z >> 16,     rowb + 5, k6, r6);
                    insK<6>(v.w & 0xFFFFu, rowb + 6, k6, r6);
                    insK<6>(v.w >> 16,     rowb + 7, k6, r6);
                }
            }
        }
        __syncthreads();   // selcta reads done before w_key reuse
        warp_top32<6>(k6, r6, w_key, w_row, wid, lane);
        __syncthreads();
        const unsigned mk = w_key[tid];
        const int      mr = w_row[tid];
        int rank = 0;
        for (int j = 0; j < 8 * K_CAND; j++)
            rank += better_pk(w_key[j], w_row[j], mk, mr) ? 1 : 0;
        if (rank < K_CAND) cid[rank] = mr;
    }
    __syncthreads();

    // ---- phase 3: exact fp32 rescore + final top-10 ----
    for (int cc = wid; cc < K_CAND; cc += 8) {
        const int idx = cid[cc];
        float dot = 0.f, nn = 0.f;
        if (idx >= 0 && idx < N) {
            const float* row = db + (size_t)idx * DIM;
            for (int i = lane; i < DIM; i += 32) {
                float d = row[i];
                dot += qsh[i] * d;
                nn  += d * d;
            }
        }
#pragma unroll
        for (int o = 16; o > 0; o >>= 1) {
            dot += __shfl_xor_sync(0xffffffff, dot, o);
            nn  += __shfl_xor_sync(0xffffffff, nn, o);
        }
        if (lane == 0)
            cex[cc] = (idx >= 0 && idx < N)
                          ? dot / fmaxf(sqrtf(nn), 1e-12f)
                          : -FLT_MAX;
    }
    __syncthreads();

    if (tid < K_CAND) {
        const float mv = cex[tid];
        const int   mi = cid[tid];
        int rank = 0;
        for (int j = 0; j < K_CAND; j++)
            rank += better_f(cex[j], cid[j], mv, mi) ? 1 : 0;
        if (rank < TOPK) {
            out[q * TOPK + rank]             = mv;
            out[Bq * TOPK + q * TOPK + rank] = (float)mi;
        }
    }
}

// ---------------------------------------------------------------------------
extern "C" void kernel_launch(void* const* d_in, const int* in_sizes, int n_in,
                              void* d_out, int out_size) {
    const float* query = (const float*)d_in[0];
    const float* db    = (const float*)d_in[1];

    int Bq = in_sizes[0] / DIM;
    int N  = in_sizes[1] / DIM;
    if (Bq > B_Q) Bq = B_Q;
    if (N > N_MAX) N = N_MAX;

    float* out = (float*)d_out;

    static bool attr_set = false;
    if (!attr_set) {
        cudaFuncSetAttribute(gemm_tc, cudaFuncAttributeMaxDynamicSharedMemorySize,
                             SM_TOTAL);
        attr_set = true;
    }

    const int nblk = (N + BLK_M - 1) / BLK_M;   // 1954

    normalize_q<<<Bq, 256>>>(query);                      // 0
    gemm_tc<<<nblk, 256, SM_TOTAL>>>(db, N);              // 1
    select_finalize<<<Bq, 256>>>(db, out, N, Bq, nblk);   // 2
    (void)n_in; (void)out_size;
}

// round 15
// speedup vs baseline: 1.2135x; 1.0281x over previous
#include <cuda_runtime.h>
#include <cuda_bf16.h>
#include <math.h>
#include <float.h>

#define DIM     768
#define B_Q     64
#define N_MAX   500000
#define TOPK    10
#define K_CAND  32

#define BLK_M   256
#define BLK_K   64          // 256 B per db row per chunk -> DRAM page locality
#define NSTAGE  3
#define STROW   64          // fp32 stage row stride (floats) = 256 B, swizzled
#define PADB    72          // bf16 q tile row stride (elements) -> conflict-free

#define NPAD       524288   // padded row count
#define NCTA_PAD   2048     // padded CTA count (>= 1954)

// ---- static device scratch (no cudaMalloc anywhere) ----
__device__ float          g_qn[B_Q * DIM];
__device__ __nv_bfloat16  g_qn_bf[B_Q * DIM];
__device__ unsigned short g_key[(size_t)B_Q * NPAD];            // 64 MB
__device__ unsigned short g_ctamax[B_Q * NCTA_PAD];             // 256 KB (pad stays 0)

// smem layout for gemm (bytes)
#define SM_STAGE   0                                     // 3*256*64*4 = 196608
#define SM_QBF     (NSTAGE * BLK_M * STROW * 4)          // 196608
#define SM_TOTAL   (SM_QBF + NSTAGE * 64 * PADB * 2)     // 224256

// ---------------------------------------------------------------------------
__device__ __forceinline__ unsigned short key16(float f) {
    unsigned short us = __bfloat16_as_ushort(__float2bfloat16_rn(f));
    return (us & 0x8000) ? (unsigned short)(~us) : (unsigned short)(us | 0x8000);
}

__device__ __forceinline__ bool better_pk(unsigned ka, int ra, unsigned kb, int rb) {
    return (ka > kb) || (ka == kb && ra < rb);
}
__device__ __forceinline__ bool better_f(float va, int ia, float vb, int ib) {
    return (va > vb) || (va == vb && ia < ib);
}

template <int D>
__device__ __forceinline__ void insK(unsigned k, int r, unsigned* ks, int* rs) {
    if (better_pk(k, r, ks[D - 1], rs[D - 1])) {
        unsigned ck = k; int cr = r;
#pragma unroll
        for (int t = 0; t < D; t++) {
            if (better_pk(ck, cr, ks[t], rs[t])) {
                unsigned tk = ks[t]; int tr = rs[t];
                ks[t] = ck; rs[t] = cr;
                ck = tk; cr = tr;
            }
        }
    }
}

// warp-wide top-32 extraction from per-thread sorted (desc) depth-D lists
template <int D>
__device__ __forceinline__ void warp_top32(unsigned* ks, int* rs,
                                           unsigned* w_key, int* w_row,
                                           int wid, int lane) {
    unsigned curk = ks[0];
    int      curr = rs[0];
    int      pos  = 0;
#pragma unroll 1
    for (int round = 0; round < K_CAND; round++) {
        unsigned bk = curk; int br = curr;
#pragma unroll
        for (int o = 16; o > 0; o >>= 1) {
            unsigned ok  = __shfl_xor_sync(0xffffffff, bk, o);
            int      orr = __shfl_xor_sync(0xffffffff, br, o);
            if (better_pk(ok, orr, bk, br)) { bk = ok; br = orr; }
        }
        if (lane == round) {
            w_key[wid * K_CAND + round] = bk;
            w_row[wid * K_CAND + round] = br;
        }
        if (curk == bk && curr == br) {
            pos++;
#pragma unroll
            for (int t = 1; t < D; t++)
                if (pos == t) { curk = ks[t]; curr = rs[t]; }
            if (pos >= D) { curk = 0u; curr = 0x7fffffff; }
        }
    }
}

// ---------------------------------------------------------------------------
// Kernel 1: L2-normalize queries; write fp32 + bf16 copies.
// ---------------------------------------------------------------------------
__global__ __launch_bounds__(256) void normalize_q(const float* __restrict__ q) {
    __shared__ float red[256];
    const int b = blockIdx.x;
    const float* row = q + (size_t)b * DIM;
    float ss = 0.f;
    for (int i = threadIdx.x; i < DIM; i += 256) {
        float v = row[i];
        ss += v * v;
    }
    red[threadIdx.x] = ss;
    __syncthreads();
    for (int s = 128; s > 0; s >>= 1) {
        if (threadIdx.x < s) red[threadIdx.x] += red[threadIdx.x + s];
        __syncthreads();
    }
    const float inv = 1.0f / fmaxf(sqrtf(red[0]), 1e-12f);
    for (int i = threadIdx.x; i < DIM; i += 256) {
        float v = row[i] * inv;
        g_qn[b * DIM + i]    = v;
        g_qn_bf[b * DIM + i] = __float2bfloat16_rn(v);
    }
}

__device__ __forceinline__ void cp16(void* dst_smem, const void* src) {
    unsigned d = (unsigned)__cvta_generic_to_shared(dst_smem);
    asm volatile("cp.async.cg.shared.global [%0], [%1], 16;" :: "r"(d), "l"(src));
}

// ---------------------------------------------------------------------------
// Kernel 2: bf16 GEMM, BLK_K=64 (256 B/row per chunk), 3-stage pipeline,
//   swizzled stage, inline fp32->bf16 fragment conversion, fused row norms,
//   key epilogue + per-CTA max. 1 CTA/SM (219.6 KB smem), 8 warps.
// ---------------------------------------------------------------------------
__global__ __launch_bounds__(256, 1) void gemm_tc(const float* __restrict__ db,
                                                  int N) {
    extern __shared__ char smc[];
    float*          stage = reinterpret_cast<float*>(smc + SM_STAGE);
    __nv_bfloat16*  q_bf  = reinterpret_cast<__nv_bfloat16*>(smc + SM_QBF);

    const int tid  = threadIdx.x;
    const int lane = tid & 31;
    const int warp = tid >> 5;
    const int gid  = lane >> 2;
    const int tig  = lane & 3;
    const int r0   = blockIdx.x * BLK_M;
    const int vx   = (gid & 3) << 1;     // frag-read swizzle (row&3 == gid&3)

    float acc[2][8][4];
#pragma unroll
    for (int mt = 0; mt < 2; mt++)
#pragma unroll
        for (int nt = 0; nt < 8; nt++)
#pragma unroll
            for (int k = 0; k < 4; k++) acc[mt][nt][k] = 0.f;

    float nacc[2][2] = {{0.f, 0.f}, {0.f, 0.f}};
    const int NC = DIM / BLK_K;   // 12

    auto issue = [&](int c, int s) {
        const int k0 = c * BLK_K;
        float* st = stage + s * BLK_M * STROW;
        // db: 256 rows x 256B = 4096 x 16B segments, 16 per thread (swizzled)
#pragma unroll
        for (int i = 0; i < 16; i++) {
            int idx = tid + i * 256;
            int row = idx >> 4;
            int jj  = idx & 15;
            int gr  = r0 + row;
            if (gr >= N) gr = N - 1;
            int sj = jj ^ ((row & 3) << 1);
            cp16(st + row * STROW + sj * 4, db + (size_t)gr * DIM + k0 + jj * 4);
        }
        // q: 64 rows x 128B = 512 x 16B segments, 2 per thread
#pragma unroll
        for (int i = 0; i < 2; i++) {
            int idx = tid + i * 256;
            int row = idx >> 3;
            int seg = idx & 7;
            cp16(q_bf + s * 64 * PADB + row * PADB + seg * 8,
                 g_qn_bf + row * DIM + k0 + seg * 8);
        }
        asm volatile("cp.async.commit_group;");
    };

    issue(0, 0);
    issue(1, 1);

    int s = 0;
    for (int c = 0; c < NC; c++) {
        if (c < NC - 1) asm volatile("cp.async.wait_group 1;");
        else            asm volatile("cp.async.wait_group 0;");
        __syncthreads();                 // stage s ready; stage (s+2)%3 free
        if (c + 2 < NC) {
            int sp = s + 2; if (sp >= NSTAGE) sp -= NSTAGE;
            issue(c + 2, sp);            // overlaps mma below
        }

        const float*         stg = stage + s * BLK_M * STROW;
        const __nv_bfloat16* qb  = q_bf + s * 64 * PADB;

#pragma unroll
        for (int ks = 0; ks < BLK_K; ks += 16) {
            const int f0 = ks + 2 * tig;
            const int f2 = f0 + 8;
            const int o0 = ((((f0 >> 2) ^ vx) << 2) | (f0 & 3));
            const int o2 = ((((f2 >> 2) ^ vx) << 2) | (f2 & 3));

            unsigned a[2][4], b[8][2];
#pragma unroll
            for (int mt = 0; mt < 2; mt++) {
                const float* rp = stg + (warp * 32 + mt * 16 + gid) * STROW;
                float2 p0 = *reinterpret_cast<const float2*>(rp + o0);
                float2 p1 = *reinterpret_cast<const float2*>(rp + 8 * STROW + o0);
                float2 p2 = *reinterpret_cast<const float2*>(rp + o2);
                float2 p3 = *reinterpret_cast<const float2*>(rp + 8 * STROW + o2);
                nacc[mt][0] += p0.x * p0.x + p0.y * p0.y + p2.x * p2.x + p2.y * p2.y;
                nacc[mt][1] += p1.x * p1.x + p1.y * p1.y + p3.x * p3.x + p3.y * p3.y;
                __nv_bfloat162 b0 = __float22bfloat162_rn(p0);
                __nv_bfloat162 b1 = __float22bfloat162_rn(p1);
                __nv_bfloat162 b2 = __float22bfloat162_rn(p2);
                __nv_bfloat162 b3 = __float22bfloat162_rn(p3);
                a[mt][0] = *reinterpret_cast<unsigned*>(&b0);
                a[mt][1] = *reinterpret_cast<unsigned*>(&b1);
                a[mt][2] = *reinterpret_cast<unsigned*>(&b2);
                a[mt][3] = *reinterpret_cast<unsigned*>(&b3);
            }
#pragma unroll
            for (int nt = 0; nt < 8; nt++) {
                const __nv_bfloat16* bp = qb + (nt * 8 + gid) * PADB + ks + 2 * tig;
                b[nt][0] = *reinterpret_cast<const unsigned*>(bp);
                b[nt][1] = *reinterpret_cast<const unsigned*>(bp + 8);
            }
#pragma unroll
            for (int mt = 0; mt < 2; mt++)
#pragma unroll
                for (int nt = 0; nt < 8; nt++) {
                    float* c4 = acc[mt][nt];
                    asm volatile(
                        "mma.sync.aligned.m16n8k16.row.col.f32.bf16.bf16.f32 "
                        "{%0,%1,%2,%3},{%4,%5,%6,%7},{%8,%9},{%0,%1,%2,%3};"
                        : "+f"(c4[0]), "+f"(c4[1]), "+f"(c4[2]), "+f"(c4[3])
                        : "r"(a[mt][0]), "r"(a[mt][1]), "r"(a[mt][2]), "r"(a[mt][3]),
                          "r"(b[nt][0]), "r"(b[nt][1]));
                }
        }
        s++; if (s >= NSTAGE) s = 0;
    }

    // row norms: sum across the 4 tig lanes (each k read exactly once)
    float inv_r[2][2];
#pragma unroll
    for (int mt = 0; mt < 2; mt++)
#pragma unroll
        for (int h = 0; h < 2; h++) {
            float v = nacc[mt][h];
            v += __shfl_xor_sync(0xffffffffu, v, 1);
            v += __shfl_xor_sync(0xffffffffu, v, 2);
            inv_r[mt][h] = 1.f / fmaxf(sqrtf(v), 1e-12f);
        }
    __syncthreads();   // all frag reads done before key overlay

    // epilogue: pack 16-bit keys into smem overlay (stage region, 32 KB)
    unsigned short* skey = reinterpret_cast<unsigned short*>(smc);  // [64][256]

#pragma unroll
    for (int mt = 0; mt < 2; mt++) {
        const int lr0 = warp * 32 + mt * 16 + gid;
        const float inv0 = inv_r[mt][0];
        const float inv1 = inv_r[mt][1];
        const int gr0 = r0 + lr0;
#pragma unroll
        for (int nt = 0; nt < 8; nt++) {
            const int q = nt * 8 + 2 * tig;
            skey[q * 256 + lr0]           = (gr0 < N)     ? key16(acc[mt][nt][0] * inv0) : (unsigned short)0;
            skey[(q + 1) * 256 + lr0]     = (gr0 < N)     ? key16(acc[mt][nt][1] * inv0) : (unsigned short)0;
            skey[q * 256 + lr0 + 8]       = (gr0 + 8 < N) ? key16(acc[mt][nt][2] * inv1) : (unsigned short)0;
            skey[(q + 1) * 256 + lr0 + 8] = (gr0 + 8 < N) ? key16(acc[mt][nt][3] * inv1) : (unsigned short)0;
        }
    }
    __syncthreads();

    // copy out keys (coalesced) + per-(q, CTA) max via warp reduction
    const uint4* src = reinterpret_cast<const uint4*>(skey);
#pragma unroll
    for (int i = 0; i < 8; i++) {
        int idx = tid + i * 256;
        int q   = idx >> 5;          // all 32 lanes of this warp share q
        int seg = idx & 31;
        uint4 v = src[idx];
        *reinterpret_cast<uint4*>(g_key + (size_t)q * NPAD + r0 + seg * 8) = v;

        unsigned m2 = __vmaxu2(__vmaxu2(v.x, v.y), __vmaxu2(v.z, v.w));
        unsigned m = max(m2 >> 16, m2 & 0xFFFFu);
#pragma unroll
        for (int o = 16; o > 0; o >>= 1)
            m = max(m, __shfl_xor_sync(0xffffffffu, m, o));
        if (lane == 0)
            g_ctamax[q * NCTA_PAD + blockIdx.x] = (unsigned short)m;
    }
}

// ---------------------------------------------------------------------------
// Kernel 3 (fused): per query — top-32 CTAs, gather their keys, top-32 rows,
//   exact fp32 rescore, emit top-10. One block (256 thr) per query.
// ---------------------------------------------------------------------------
__global__ __launch_bounds__(256) void select_finalize(const float* __restrict__ db,
                                                       float* __restrict__ out,
                                                       int N, int Bq, int NCTA) {
    __shared__ unsigned w_key[8 * K_CAND];
    __shared__ int      w_row[8 * K_CAND];
    __shared__ int      selcta[K_CAND];
    __shared__ float    qsh[DIM];
    __shared__ int      cid[K_CAND];
    __shared__ float    cex[K_CAND];

    const int q    = blockIdx.x;
    const int tid  = threadIdx.x;
    const int lane = tid & 31;
    const int wid  = tid >> 5;

    for (int i = tid; i < DIM; i += 256) qsh[i] = g_qn[q * DIM + i];

    // ---- phase 1: top-32 CTAs by (max desc, id asc); vectorized uint4 load ----
    {
        unsigned k8[8]; int r8[8];
#pragma unroll
        for (int t = 0; t < 8; t++) { k8[t] = 0; r8[t] = 0x7fffffff; }
        uint4 v = *reinterpret_cast<const uint4*>(g_ctamax + q * NCTA_PAD + tid * 8);
        const int base = tid * 8;
        insK<8>(v.x & 0xFFFFu, base + 0, k8, r8);
        insK<8>(v.x >> 16,     base + 1, k8, r8);
        insK<8>(v.y & 0xFFFFu, base + 2, k8, r8);
        insK<8>(v.y >> 16,     base + 3, k8, r8);
        insK<8>(v.z & 0xFFFFu, base + 4, k8, r8);
        insK<8>(v.z >> 16,     base + 5, k8, r8);
        insK<8>(v.w & 0xFFFFu, base + 6, k8, r8);
        insK<8>(v.w >> 16,     base + 7, k8, r8);

        warp_top32<8>(k8, r8, w_key, w_row, wid, lane);
        __syncthreads();
        const unsigned mk = w_key[tid];
        const int      mr = w_row[tid];
        int rank = 0;
        for (int j = 0; j < 8 * K_CAND; j++)
            rank += better_pk(w_key[j], w_row[j], mk, mr) ? 1 : 0;
        if (rank < K_CAND) selcta[rank] = mr;
    }
    __syncthreads();

    // ---- phase 2: gather 32 CTA tiles (8192 keys), top-32 rows ----
    {
        unsigned k6[6]; int r6[6];
#pragma unroll
        for (int t = 0; t < 6; t++) { k6[t] = 0; r6[t] = 0x7fffffff; }
#pragma unroll
        for (int rep = 0; rep < 4; rep++) {
            const int slot = (tid >> 5) + rep * 8;
            const int u4   = tid & 31;
            const int cta  = selcta[slot];
            if (cta >= 0 && cta < NCTA) {
                const int rowb = cta * 256 + u4 * 8;
                uint4 v = *reinterpret_cast<const uint4*>(g_key + (size_t)q * NPAD + rowb);
                unsigned m2 = __vmaxu2(__vmaxu2(v.x, v.y), __vmaxu2(v.z, v.w));
                unsigned hm = max(m2 >> 16, m2 & 0xFFFFu);
                if (hm > k6[5]) {
                    insK<6>(v.x & 0xFFFFu, rowb + 0, k6, r6);
                    insK<6>(v.x >> 16,     rowb + 1, k6, r6);
                    insK<6>(v.y & 0xFFFFu, rowb + 2, k6, r6);
                    insK<6>(v.y >> 16,     rowb + 3, k6, r6);
                    insK<6>(v.z & 0xFFFFu, rowb + 4, k6, r6);
                    insK<6>(v.z >> 16,     rowb + 5, k6, r6);
                    insK<6>(v.w & 0xFFFFu, rowb + 6, k6, r6);
                    insK<6>(v.w >> 16,     rowb + 7, k6, r6);
                }
            }
        }
        __syncthreads();   // selcta reads done before w_key reuse
        warp_top32<6>(k6, r6, w_key, w_row, wid, lane);
        __syncthreads();
        const unsigned mk = w_key[tid];
        const int      mr = w_row[tid];
        int rank = 0;
        for (int j = 0; j < 8 * K_CAND; j++)
            rank += better_pk(w_key[j], w_row[j], mk, mr) ? 1 : 0;
        if (rank < K_CAND) cid[rank] = mr;
    }
    __syncthreads();

    // ---- phase 3: exact fp32 rescore + final top-10 ----
    for (int cc = wid; cc < K_CAND; cc += 8) {
        const int idx = cid[cc];
        float dot = 0.f, nn = 0.f;
        if (idx >= 0 && idx < N) {
            const float* row = db + (size_t)idx * DIM;
            for (int i = lane; i < DIM; i += 32) {
                float d = row[i];
                dot += qsh[i] * d;
                nn  += d * d;
            }
        }
#pragma unroll
        for (int o = 16; o > 0; o >>= 1) {
            dot += __shfl_xor_sync(0xffffffff, dot, o);
            nn  += __shfl_xor_sync(0xffffffff, nn, o);
        }
        if (lane == 0)
            cex[cc] = (idx >= 0 && idx < N)
                          ? dot / fmaxf(sqrtf(nn), 1e-12f)
                          : -FLT_MAX;
    }
    __syncthreads();

    if (tid < K_CAND) {
        const float mv = cex[tid];
        const int   mi = cid[tid];
        int rank = 0;
        for (int j = 0; j < K_CAND; j++)
            rank += better_f(cex[j], cid[j], mv, mi) ? 1 : 0;
        if (rank < TOPK) {
            out[q * TOPK + rank]             = mv;
            out[Bq * TOPK + q * TOPK + rank] = (float)mi;
        }
    }
}

// ---------------------------------------------------------------------------
extern "C" void kernel_launch(void* const* d_in, const int* in_sizes, int n_in,
                              void* d_out, int out_size) {
    const float* query = (const float*)d_in[0];
    const float* db    = (const float*)d_in[1];

    int Bq = in_sizes[0] / DIM;
    int N  = in_sizes[1] / DIM;
    if (Bq > B_Q) Bq = B_Q;
    if (N > N_MAX) N = N_MAX;

    float* out = (float*)d_out;

    static bool attr_set = false;
    if (!attr_set) {
        cudaFuncSetAttribute(gemm_tc, cudaFuncAttributeMaxDynamicSharedMemorySize,
                             SM_TOTAL);
        attr_set = true;
    }

    const int nblk = (N + BLK_M - 1) / BLK_M;   // 1954

    normalize_q<<<Bq, 256>>>(query);                      // 0
    gemm_tc<<<nblk, 256, SM_TOTAL>>>(db, N);              // 1
    select_finalize<<<Bq, 256>>>(db, out, N, Bq, nblk);   // 2
    (void)n_in; (void)out_size;
}

// round 16
// speedup vs baseline: 1.2199x; 1.0053x over previous
#include <cuda_runtime.h>
#include <cuda_bf16.h>
#include <math.h>
#include <float.h>

#define DIM     768
#define B_Q     64
#define N_MAX   500000
#define TOPK    10
#define K_CAND  32

#define BLK_M   256
#define BLK_K   64          // 256 B per db row per chunk -> DRAM page locality
#define NSTAGE  3
#define STROW   64          // fp32 stage row stride (floats) = 256 B, swizzled
#define PADB    72          // bf16 q tile row stride (elements) -> conflict-free
#define NC      (DIM / BLK_K)   // 12 chunks per tile (12 % 3 == 0 -> buf pattern fixed)

#define NPAD       524288   // padded row count
#define NCTA_PAD   2048     // padded tile count (>= 1954)

// ---- static device scratch (no cudaMalloc anywhere) ----
__device__ float          g_qn[B_Q * DIM];
__device__ __nv_bfloat16  g_qn_bf[B_Q * DIM];
__device__ unsigned short g_key[(size_t)B_Q * NPAD];            // 64 MB
__device__ unsigned short g_ctamax[B_Q * NCTA_PAD];             // 256 KB (pad stays 0)
__device__ float          g_dummy[64];

// smem layout for gemm (bytes)
#define SM_STAGE   0                                     // 3*256*64*4 = 196608
#define SM_QBF     (NSTAGE * BLK_M * STROW * 4)          // 196608
#define SM_TOTAL   (SM_QBF + NSTAGE * 64 * PADB * 2)     // 224256
#define SM_SKEY    (2 * BLK_M * STROW * 4)               // buffer 2 (tile-final buf)

// ---------------------------------------------------------------------------
__device__ __forceinline__ unsigned short key16(float f) {
    unsigned short us = __bfloat16_as_ushort(__float2bfloat16_rn(f));
    return (us & 0x8000) ? (unsigned short)(~us) : (unsigned short)(us | 0x8000);
}

__device__ __forceinline__ bool better_pk(unsigned ka, int ra, unsigned kb, int rb) {
    return (ka > kb) || (ka == kb && ra < rb);
}
__device__ __forceinline__ bool better_f(float va, int ia, float vb, int ib) {
    return (va > vb) || (va == vb && ia < ib);
}

template <int D>
__device__ __forceinline__ void insK(unsigned k, int r, unsigned* ks, int* rs) {
    if (better_pk(k, r, ks[D - 1], rs[D - 1])) {
        unsigned ck = k; int cr = r;
#pragma unroll
        for (int t = 0; t < D; t++) {
            if (better_pk(ck, cr, ks[t], rs[t])) {
                unsigned tk = ks[t]; int tr = rs[t];
                ks[t] = ck; rs[t] = cr;
                ck = tk; cr = tr;
            }
        }
    }
}

// warp-wide top-32 extraction from per-thread sorted (desc) depth-D lists
template <int D>
__device__ __forceinline__ void warp_top32(unsigned* ks, int* rs,
                                           unsigned* w_key, int* w_row,
                                           int wid, int lane) {
    unsigned curk = ks[0];
    int      curr = rs[0];
    int      pos  = 0;
#pragma unroll 1
    for (int round = 0; round < K_CAND; round++) {
        unsigned bk = curk; int br = curr;
#pragma unroll
        for (int o = 16; o > 0; o >>= 1) {
            unsigned ok  = __shfl_xor_sync(0xffffffff, bk, o);
            int      orr = __shfl_xor_sync(0xffffffff, br, o);
            if (better_pk(ok, orr, bk, br)) { bk = ok; br = orr; }
        }
        if (lane == round) {
            w_key[wid * K_CAND + round] = bk;
            w_row[wid * K_CAND + round] = br;
        }
        if (curk == bk && curr == br) {
            pos++;
#pragma unroll
            for (int t = 1; t < D; t++)
                if (pos == t) { curk = ks[t]; curr = rs[t]; }
            if (pos >= D) { curk = 0u; curr = 0x7fffffff; }
        }
    }
}

// ---------------------------------------------------------------------------
// Kernel 1: L2-normalize queries; write fp32 + bf16 copies.
// ---------------------------------------------------------------------------
__global__ __launch_bounds__(256) void normalize_q(const float* __restrict__ q) {
    __shared__ float red[256];
    const int b = blockIdx.x;
    const float* row = q + (size_t)b * DIM;
    float ss = 0.f;
    for (int i = threadIdx.x; i < DIM; i += 256) {
        float v = row[i];
        ss += v * v;
    }
    red[threadIdx.x] = ss;
    __syncthreads();
    for (int s = 128; s > 0; s >>= 1) {
        if (threadIdx.x < s) red[threadIdx.x] += red[threadIdx.x + s];
        __syncthreads();
    }
    const float inv = 1.0f / fmaxf(sqrtf(red[0]), 1e-12f);
    for (int i = threadIdx.x; i < DIM; i += 256) {
        float v = row[i] * inv;
        g_qn[b * DIM + i]    = v;
        g_qn_bf[b * DIM + i] = __float2bfloat16_rn(v);
    }
}

__global__ void prep1() { if (threadIdx.x < 64) g_dummy[threadIdx.x] = 0.f; }
__global__ void prep2() { if (threadIdx.x < 64) g_dummy[threadIdx.x] = 1.f; }

__device__ __forceinline__ void cp16(void* dst_smem, const void* src) {
    unsigned d = (unsigned)__cvta_generic_to_shared(dst_smem);
    asm volatile("cp.async.cg.shared.global [%0], [%1], 16;" :: "r"(d), "l"(src));
}

// ---------------------------------------------------------------------------
// Kernel 2: PERSISTENT bf16 GEMM. Grid = 152 (1 CTA/SM); each CTA loops
//   tiles bid, bid+grid, ... with ONE continuous 3-stage cp.async pipeline
//   across tile boundaries (no per-tile drain/fill DRAM gaps).
//   Tile-final chunk always lands in buffer 2 (NC%3==0) -> epilogue skey
//   overlay uses buffer 2 while buffers 0/1 carry next tile's loads.
// ---------------------------------------------------------------------------
__global__ __launch_bounds__(256, 1) void gemm_tc(const float* __restrict__ db,
                                                  int N, int NTILE) {
    extern __shared__ char smc[];
    float*          stage = reinterpret_cast<float*>(smc + SM_STAGE);
    __nv_bfloat16*  q_bf  = reinterpret_cast<__nv_bfloat16*>(smc + SM_QBF);

    const int tid  = threadIdx.x;
    const int lane = tid & 31;
    const int warp = tid >> 5;
    const int gid  = lane >> 2;
    const int tig  = lane & 3;
    const int bid  = blockIdx.x;
    const int GRID = gridDim.x;
    const int vx   = (gid & 3) << 1;     // frag-read swizzle (row&3 == gid&3)

    if (bid >= NTILE) return;
    const int count = (NTILE - bid + GRID - 1) / GRID;   // tiles for this CTA
    const int G     = count * NC;                        // total chunks

    float acc[2][8][4];
#pragma unroll
    for (int mt = 0; mt < 2; mt++)
#pragma unroll
        for (int nt = 0; nt < 8; nt++)
#pragma unroll
            for (int k = 0; k < 4; k++) acc[mt][nt][k] = 0.f;

    float nacc[2][2] = {{0.f, 0.f}, {0.f, 0.f}};

    auto issue_g = [&](int g) {
        const int ti   = g / NC;
        const int c    = g - ti * NC;
        const int r0t  = (bid + ti * GRID) * BLK_M;
        const int k0   = c * BLK_K;
        const int sb   = g % 3;
        float* st = stage + sb * BLK_M * STROW;
        // db: 256 rows x 256B = 4096 x 16B segments, 16 per thread (swizzled)
#pragma unroll
        for (int i = 0; i < 16; i++) {
            int idx = tid + i * 256;
            int row = idx >> 4;
            int jj  = idx & 15;
            int gr  = r0t + row;
            if (gr >= N) gr = N - 1;
            int sj = jj ^ ((row & 3) << 1);
            cp16(st + row * STROW + sj * 4, db + (size_t)gr * DIM + k0 + jj * 4);
        }
        // q: 64 rows x 128B = 512 x 16B segments, 2 per thread
#pragma unroll
        for (int i = 0; i < 2; i++) {
            int idx = tid + i * 256;
            int row = idx >> 3;
            int seg = idx & 7;
            cp16(q_bf + sb * 64 * PADB + row * PADB + seg * 8,
                 g_qn_bf + row * DIM + k0 + seg * 8);
        }
        asm volatile("cp.async.commit_group;");
    };

    issue_g(0);
    issue_g(1);

    for (int g = 0; g < G; g++) {
        const int sb = g % 3;
        const int c  = g % NC;
        if (g < G - 1) asm volatile("cp.async.wait_group 1;");
        else           asm volatile("cp.async.wait_group 0;");
        __syncthreads();                 // chunk g ready; buffer (g+3)%3 safe to fill
        if (g + 2 < G) issue_g(g + 2);   // overlaps mma below (possibly next tile)

        const float*         stg = stage + sb * BLK_M * STROW;
        const __nv_bfloat16* qb  = q_bf + sb * 64 * PADB;

#pragma unroll
        for (int ks = 0; ks < BLK_K; ks += 16) {
            const int f0 = ks + 2 * tig;
            const int f2 = f0 + 8;
            const int o0 = ((((f0 >> 2) ^ vx) << 2) | (f0 & 3));
            const int o2 = ((((f2 >> 2) ^ vx) << 2) | (f2 & 3));

            unsigned a[2][4], b[8][2];
#pragma unroll
            for (int mt = 0; mt < 2; mt++) {
                const float* rp = stg + (warp * 32 + mt * 16 + gid) * STROW;
                float2 p0 = *reinterpret_cast<const float2*>(rp + o0);
                float2 p1 = *reinterpret_cast<const float2*>(rp + 8 * STROW + o0);
                float2 p2 = *reinterpret_cast<const float2*>(rp + o2);
                float2 p3 = *reinterpret_cast<const float2*>(rp + 8 * STROW + o2);
                nacc[mt][0] += p0.x * p0.x + p0.y * p0.y + p2.x * p2.x + p2.y * p2.y;
                nacc[mt][1] += p1.x * p1.x + p1.y * p1.y + p3.x * p3.x + p3.y * p3.y;
                __nv_bfloat162 b0 = __float22bfloat162_rn(p0);
                __nv_bfloat162 b1 = __float22bfloat162_rn(p1);
                __nv_bfloat162 b2 = __float22bfloat162_rn(p2);
                __nv_bfloat162 b3 = __float22bfloat162_rn(p3);
                a[mt][0] = *reinterpret_cast<unsigned*>(&b0);
                a[mt][1] = *reinterpret_cast<unsigned*>(&b1);
                a[mt][2] = *reinterpret_cast<unsigned*>(&b2);
                a[mt][3] = *reinterpret_cast<unsigned*>(&b3);
            }
#pragma unroll
            for (int nt = 0; nt < 8; nt++) {
                const __nv_bfloat16* bp = qb + (nt * 8 + gid) * PADB + ks + 2 * tig;
                b[nt][0] = *reinterpret_cast<const unsigned*>(bp);
                b[nt][1] = *reinterpret_cast<const unsigned*>(bp + 8);
            }
#pragma unroll
            for (int mt = 0; mt < 2; mt++)
#pragma unroll
                for (int nt = 0; nt < 8; nt++) {
                    float* c4 = acc[mt][nt];
                    asm volatile(
                        "mma.sync.aligned.m16n8k16.row.col.f32.bf16.bf16.f32 "
                        "{%0,%1,%2,%3},{%4,%5,%6,%7},{%8,%9},{%0,%1,%2,%3};"
                        : "+f"(c4[0]), "+f"(c4[1]), "+f"(c4[2]), "+f"(c4[3])
                        : "r"(a[mt][0]), "r"(a[mt][1]), "r"(a[mt][2]), "r"(a[mt][3]),
                          "r"(b[nt][0]), "r"(b[nt][1]));
                }
        }

        // ---- tile epilogue (c == NC-1): buffer 2 is free until chunk g+3 ----
        if (c == NC - 1) {
            const int tile = bid + (g / NC) * GRID;
            const int r0t  = tile * BLK_M;

            float inv_r[2][2];
#pragma unroll
            for (int mt = 0; mt < 2; mt++)
#pragma unroll
                for (int h = 0; h < 2; h++) {
                    float v = nacc[mt][h];
                    v += __shfl_xor_sync(0xffffffffu, v, 1);
                    v += __shfl_xor_sync(0xffffffffu, v, 2);
                    inv_r[mt][h] = 1.f / fmaxf(sqrtf(v), 1e-12f);
                    nacc[mt][h] = 0.f;
                }
            __syncthreads();   // all frag reads of buffer 2 done before overlay

            unsigned short* skey = reinterpret_cast<unsigned short*>(smc + SM_SKEY);

#pragma unroll
            for (int mt = 0; mt < 2; mt++) {
                const int lr0 = warp * 32 + mt * 16 + gid;
                const float inv0 = inv_r[mt][0];
                const float inv1 = inv_r[mt][1];
                const int gr0 = r0t + lr0;
#pragma unroll
                for (int nt = 0; nt < 8; nt++) {
                    const int q = nt * 8 + 2 * tig;
                    skey[q * 256 + lr0]           = (gr0 < N)     ? key16(acc[mt][nt][0] * inv0) : (unsigned short)0;
                    skey[(q + 1) * 256 + lr0]     = (gr0 < N)     ? key16(acc[mt][nt][1] * inv0) : (unsigned short)0;
                    skey[q * 256 + lr0 + 8]       = (gr0 + 8 < N) ? key16(acc[mt][nt][2] * inv1) : (unsigned short)0;
                    skey[(q + 1) * 256 + lr0 + 8] = (gr0 + 8 < N) ? key16(acc[mt][nt][3] * inv1) : (unsigned short)0;
                    acc[mt][nt][0] = acc[mt][nt][1] = acc[mt][nt][2] = acc[mt][nt][3] = 0.f;
                }
            }
            __syncthreads();

            // copy out keys (coalesced) + per-(q, tile) max via warp reduction
            const uint4* src = reinterpret_cast<const uint4*>(skey);
#pragma unroll
            for (int i = 0; i < 8; i++) {
                int idx = tid + i * 256;
                int q   = idx >> 5;      // all 32 lanes of this warp share q
                int seg = idx & 31;
                uint4 v = src[idx];
                *reinterpret_cast<uint4*>(g_key + (size_t)q * NPAD + r0t + seg * 8) = v;

                unsigned m2 = __vmaxu2(__vmaxu2(v.x, v.y), __vmaxu2(v.z, v.w));
                unsigned m = max(m2 >> 16, m2 & 0xFFFFu);
#pragma unroll
                for (int o = 16; o > 0; o >>= 1)
                    m = max(m, __shfl_xor_sync(0xffffffffu, m, o));
                if (lane == 0)
                    g_ctamax[q * NCTA_PAD + tile] = (unsigned short)m;
            }
            // next loop iteration's __syncthreads orders these skey reads
            // before issue_g(g+3) refills buffer 2.
        }
    }
}

// ---------------------------------------------------------------------------
// Kernel 3 (fused): per query — top-32 tiles, gather their keys, top-32 rows,
//   exact fp32 rescore, emit top-10. One block (256 thr) per query.
// ---------------------------------------------------------------------------
__global__ __launch_bounds__(256) void select_finalize(const float* __restrict__ db,
                                                       float* __restrict__ out,
                                                       int N, int Bq, int NCTA) {
    __shared__ unsigned w_key[8 * K_CAND];
    __shared__ int      w_row[8 * K_CAND];
    __shared__ int      selcta[K_CAND];
    __shared__ float    qsh[DIM];
    __shared__ int      cid[K_CAND];
    __shared__ float    cex[K_CAND];

    const int q    = blockIdx.x;
    const int tid  = threadIdx.x;
    const int lane = tid & 31;
    const int wid  = tid >> 5;

    for (int i = tid; i < DIM; i += 256) qsh[i] = g_qn[q * DIM + i];

    // ---- phase 1: top-32 tiles by (max desc, id asc); vectorized uint4 load ----
    {
        unsigned k8[8]; int r8[8];
#pragma unroll
        for (int t = 0; t < 8; t++) { k8[t] = 0; r8[t] = 0x7fffffff; }
        uint4 v = *reinterpret_cast<const uint4*>(g_ctamax + q * NCTA_PAD + tid * 8);
        const int base = tid * 8;
        insK<8>(v.x & 0xFFFFu, base + 0, k8, r8);
        insK<8>(v.x >> 16,     base + 1, k8, r8);
        insK<8>(v.y & 0xFFFFu, base + 2, k8, r8);
        insK<8>(v.y >> 16,     base + 3, k8, r8);
        insK<8>(v.z & 0xFFFFu, base + 4, k8, r8);
        insK<8>(v.z >> 16,     base + 5, k8, r8);
        insK<8>(v.w & 0xFFFFu, base + 6, k8, r8);
        insK<8>(v.w >> 16,     base + 7, k8, r8);

        warp_top32<8>(k8, r8, w_key, w_row, wid, lane);
        __syncthreads();
        const unsigned mk = w_key[tid];
        const int      mr = w_row[tid];
        int rank = 0;
        for (int j = 0; j < 8 * K_CAND; j++)
            rank += better_pk(w_key[j], w_row[j], mk, mr) ? 1 : 0;
        if (rank < K_CAND) selcta[rank] = mr;
    }
    __syncthreads();

    // ---- phase 2: gather 32 tile key-blocks (8192 keys), top-32 rows ----
    {
        unsigned k6[6]; int r6[6];
#pragma unroll
        for (int t = 0; t < 6; t++) { k6[t] = 0; r6[t] = 0x7fffffff; }
#pragma unroll
        for (int rep = 0; rep < 4; rep++) {
            const int slot = (tid >> 5) + rep * 8;
            const int u4   = tid & 31;
            const int cta  = selcta[slot];
            if (cta >= 0 && cta < NCTA) {
                const int rowb = cta * 256 + u4 * 8;
                uint4 v = *reinterpret_cast<const uint4*>(g_key + (size_t)q * NPAD + rowb);
                unsigned m2 = __vmaxu2(__vmaxu2(v.x, v.y), __vmaxu2(v.z, v.w));
                unsigned hm = max(m2 >> 16, m2 & 0xFFFFu);
                if (hm > k6[5]) {
                    insK<6>(v.x & 0xFFFFu, rowb + 0, k6, r6);
                    insK<6>(v.x >> 16,     rowb + 1, k6, r6);
                    insK<6>(v.y & 0xFFFFu, rowb + 2, k6, r6);
                    insK<6>(v.y >> 16,     rowb + 3, k6, r6);
                    insK<6>(v.z & 0xFFFFu, rowb + 4, k6, r6);
                    insK<6>(v.z >> 16,     rowb + 5, k6, r6);
                    insK<6>(v.w & 0xFFFFu, rowb + 6, k6, r6);
                    insK<6>(v.w >> 16,     rowb + 7, k6, r6);
                }
            }
        }
        __syncthreads();   // selcta reads done before w_key reuse
        warp_top32<6>(k6, r6, w_key, w_row, wid, lane);
        __syncthreads();
        const unsigned mk = w_key[tid];
        const int      mr = w_row[tid];
        int rank = 0;
        for (int j = 0; j < 8 * K_CAND; j++)
            rank += better_pk(w_key[j], w_row[j], mk, mr) ? 1 : 0;
        if (rank < K_CAND) cid[rank] = mr;
    }
    __syncthreads();

    // ---- phase 3: exact fp32 rescore + final top-10 ----
    for (int cc = wid; cc < K_CAND; cc += 8) {
        const int idx = cid[cc];
        float dot = 0.f, nn = 0.f;
        if (idx >= 0 && idx < N) {
            const float* row = db + (size_t)idx * DIM;
            for (int i = lane; i < DIM; i += 32) {
                float d = row[i];
                dot += qsh[i] * d;
                nn  += d * d;
            }
        }
#pragma unroll
        for (int o = 16; o > 0; o >>= 1) {
            dot += __shfl_xor_sync(0xffffffff, dot, o);
            nn  += __shfl_xor_sync(0xffffffff, nn, o);
        }
        if (lane == 0)
            cex[cc] = (idx >= 0 && idx < N)
                          ? dot / fmaxf(sqrtf(nn), 1e-12f)
                          : -FLT_MAX;
    }
    __syncthreads();

    if (tid < K_CAND) {
        const float mv = cex[tid];
        const int   mi = cid[tid];
        int rank = 0;
        for (int j = 0; j < K_CAND; j++)
            rank += better_f(cex[j], cid[j], mv, mi) ? 1 : 0;
        if (rank < TOPK) {
            out[q * TOPK + rank]             = mv;
            out[Bq * TOPK + q * TOPK + rank] = (float)mi;
        }
    }
}

// ---------------------------------------------------------------------------
extern "C" void kernel_launch(void* const* d_in, const int* in_sizes, int n_in,
                              void* d_out, int out_size) {
    const float* query = (const float*)d_in[0];
    const float* db    = (const float*)d_in[1];

    int Bq = in_sizes[0] / DIM;
    int N  = in_sizes[1] / DIM;
    if (Bq > B_Q) Bq = B_Q;
    if (N > N_MAX) N = N_MAX;

    float* out = (float*)d_out;

    static bool attr_set = false;
    if (!attr_set) {
        cudaFuncSetAttribute(gemm_tc, cudaFuncAttributeMaxDynamicSharedMemorySize,
                             SM_TOTAL);
        attr_set = true;
    }

    const int ntile = (N + BLK_M - 1) / BLK_M;   // 1954
    const int gemm_grid = 152;                   // persistent: 1 CTA/SM

    // 5 launches/iter -> ncu window (index 3 mod 5) lands on gemm_tc
    prep1<<<1, 64>>>();                                    // 0
    prep2<<<1, 64>>>();                                    // 1
    normalize_q<<<Bq, 256>>>(query);                       // 2
    gemm_tc<<<gemm_grid, 256, SM_TOTAL>>>(db, N, ntile);   // 3  (profiled)
    select_finalize<<<Bq, 256>>>(db, out, N, Bq, ntile);   // 4
    (void)n_in; (void)out_size;
}

// round 17
// speedup vs baseline: 1.2365x; 1.0136x over previous
#include <cuda_runtime.h>
#include <cuda_bf16.h>
#include <math.h>
#include <float.h>

#define DIM     768
#define B_Q     64
#define N_MAX   500000
#define TOPK    10
#define K_CAND  32

#define BLK_M   256
#define BLK_K   64          // 256 B per db row per chunk -> DRAM page locality
#define NSTAGE  3
#define STROW   64          // fp32 stage row stride (floats) = 256 B, swizzled
#define PADB    72          // bf16 q tile row stride (elements) -> conflict-free
#define NC      (DIM / BLK_K)   // 12 chunks per tile (12 % 3 == 0 -> buf pattern fixed)

#define NPAD       524288   // padded row count
#define NCTA_PAD   2048     // padded tile count (>= 1954)

// ---- static device scratch (no cudaMalloc anywhere) ----
__device__ float          g_qn[B_Q * DIM];
__device__ __nv_bfloat16  g_qn_bf[B_Q * DIM];
__device__ unsigned short g_key[(size_t)B_Q * NPAD];            // 64 MB
__device__ unsigned short g_ctamax[B_Q * NCTA_PAD];             // 256 KB (pad stays 0)

// smem layout for gemm (bytes)
#define SM_STAGE   0                                     // 3*256*64*4 = 196608
#define SM_QBF     (NSTAGE * BLK_M * STROW * 4)          // 196608
#define SM_TOTAL   (SM_QBF + NSTAGE * 64 * PADB * 2)     // 224256
#define SM_SKEY    (2 * BLK_M * STROW * 4)               // buffer 2 (tile-final buf)

// ---------------------------------------------------------------------------
__device__ __forceinline__ unsigned short key16(float f) {
    unsigned short us = __bfloat16_as_ushort(__float2bfloat16_rn(f));
    return (us & 0x8000) ? (unsigned short)(~us) : (unsigned short)(us | 0x8000);
}

__device__ __forceinline__ bool better_pk(unsigned ka, int ra, unsigned kb, int rb) {
    return (ka > kb) || (ka == kb && ra < rb);
}
__device__ __forceinline__ bool better_f(float va, int ia, float vb, int ib) {
    return (va > vb) || (va == vb && ia < ib);
}

template <int D>
__device__ __forceinline__ void insK(unsigned k, int r, unsigned* ks, int* rs) {
    if (better_pk(k, r, ks[D - 1], rs[D - 1])) {
        unsigned ck = k; int cr = r;
#pragma unroll
        for (int t = 0; t < D; t++) {
            if (better_pk(ck, cr, ks[t], rs[t])) {
                unsigned tk = ks[t]; int tr = rs[t];
                ks[t] = ck; rs[t] = cr;
                ck = tk; cr = tr;
            }
        }
    }
}

// warp-wide top-32 extraction from per-thread sorted (desc) depth-D lists
template <int D>
__device__ __forceinline__ void warp_top32(unsigned* ks, int* rs,
                                           unsigned* w_key, int* w_row,
                                           int wid, int lane) {
    unsigned curk = ks[0];
    int      curr = rs[0];
    int      pos  = 0;
#pragma unroll 1
    for (int round = 0; round < K_CAND; round++) {
        unsigned bk = curk; int br = curr;
#pragma unroll
        for (int o = 16; o > 0; o >>= 1) {
            unsigned ok  = __shfl_xor_sync(0xffffffff, bk, o);
            int      orr = __shfl_xor_sync(0xffffffff, br, o);
            if (better_pk(ok, orr, bk, br)) { bk = ok; br = orr; }
        }
        if (lane == round) {
            w_key[wid * K_CAND + round] = bk;
            w_row[wid * K_CAND + round] = br;
        }
        if (curk == bk && curr == br) {
            pos++;
#pragma unroll
            for (int t = 1; t < D; t++)
                if (pos == t) { curk = ks[t]; curr = rs[t]; }
            if (pos >= D) { curk = 0u; curr = 0x7fffffff; }
        }
    }
}

// ---------------------------------------------------------------------------
// Kernel 1: L2-normalize queries; write fp32 + bf16 copies.
// ---------------------------------------------------------------------------
__global__ __launch_bounds__(256) void normalize_q(const float* __restrict__ q) {
    __shared__ float red[256];
    const int b = blockIdx.x;
    const float* row = q + (size_t)b * DIM;
    float ss = 0.f;
    for (int i = threadIdx.x; i < DIM; i += 256) {
        float v = row[i];
        ss += v * v;
    }
    red[threadIdx.x] = ss;
    __syncthreads();
    for (int s = 128; s > 0; s >>= 1) {
        if (threadIdx.x < s) red[threadIdx.x] += red[threadIdx.x + s];
        __syncthreads();
    }
    const float inv = 1.0f / fmaxf(sqrtf(red[0]), 1e-12f);
    for (int i = threadIdx.x; i < DIM; i += 256) {
        float v = row[i] * inv;
        g_qn[b * DIM + i]    = v;
        g_qn_bf[b * DIM + i] = __float2bfloat16_rn(v);
    }
}

__device__ __forceinline__ void cp16(void* dst_smem, const void* src) {
    unsigned d = (unsigned)__cvta_generic_to_shared(dst_smem);
    asm volatile("cp.async.cg.shared.global [%0], [%1], 16;" :: "r"(d), "l"(src));
}

// ---------------------------------------------------------------------------
// Kernel 2: PERSISTENT bf16 GEMM. Grid = 152 (1 CTA/SM); each CTA loops
//   tiles bid, bid+grid, ... with ONE continuous 3-stage cp.async pipeline
//   across tile boundaries (no per-tile drain/fill DRAM gaps).
//   Tile-final chunk always lands in buffer 2 (NC%3==0) -> epilogue skey
//   overlay uses buffer 2 while buffers 0/1 carry next tile's loads.
//   (R16 winner, byte-identical.)
// ---------------------------------------------------------------------------
__global__ __launch_bounds__(256, 1) void gemm_tc(const float* __restrict__ db,
                                                  int N, int NTILE) {
    extern __shared__ char smc[];
    float*          stage = reinterpret_cast<float*>(smc + SM_STAGE);
    __nv_bfloat16*  q_bf  = reinterpret_cast<__nv_bfloat16*>(smc + SM_QBF);

    const int tid  = threadIdx.x;
    const int lane = tid & 31;
    const int warp = tid >> 5;
    const int gid  = lane >> 2;
    const int tig  = lane & 3;
    const int bid  = blockIdx.x;
    const int GRID = gridDim.x;
    const int vx   = (gid & 3) << 1;     // frag-read swizzle (row&3 == gid&3)

    if (bid >= NTILE) return;
    const int count = (NTILE - bid + GRID - 1) / GRID;   // tiles for this CTA
    const int G     = count * NC;                        // total chunks

    float acc[2][8][4];
#pragma unroll
    for (int mt = 0; mt < 2; mt++)
#pragma unroll
        for (int nt = 0; nt < 8; nt++)
#pragma unroll
            for (int k = 0; k < 4; k++) acc[mt][nt][k] = 0.f;

    float nacc[2][2] = {{0.f, 0.f}, {0.f, 0.f}};

    auto issue_g = [&](int g) {
        const int ti   = g / NC;
        const int c    = g - ti * NC;
        const int r0t  = (bid + ti * GRID) * BLK_M;
        const int k0   = c * BLK_K;
        const int sb   = g % 3;
        float* st = stage + sb * BLK_M * STROW;
        // db: 256 rows x 256B = 4096 x 16B segments, 16 per thread (swizzled)
#pragma unroll
        for (int i = 0; i < 16; i++) {
            int idx = tid + i * 256;
            int row = idx >> 4;
            int jj  = idx & 15;
            int gr  = r0t + row;
            if (gr >= N) gr = N - 1;
            int sj = jj ^ ((row & 3) << 1);
            cp16(st + row * STROW + sj * 4, db + (size_t)gr * DIM + k0 + jj * 4);
        }
        // q: 64 rows x 128B = 512 x 16B segments, 2 per thread
#pragma unroll
        for (int i = 0; i < 2; i++) {
            int idx = tid + i * 256;
            int row = idx >> 3;
            int seg = idx & 7;
            cp16(q_bf + sb * 64 * PADB + row * PADB + seg * 8,
                 g_qn_bf + row * DIM + k0 + seg * 8);
        }
        asm volatile("cp.async.commit_group;");
    };

    issue_g(0);
    issue_g(1);

    for (int g = 0; g < G; g++) {
        const int sb = g % 3;
        const int c  = g % NC;
        if (g < G - 1) asm volatile("cp.async.wait_group 1;");
        else           asm volatile("cp.async.wait_group 0;");
        __syncthreads();                 // chunk g ready; buffer (g+3)%3 safe to fill
        if (g + 2 < G) issue_g(g + 2);   // overlaps mma below (possibly next tile)

        const float*         stg = stage + sb * BLK_M * STROW;
        const __nv_bfloat16* qb  = q_bf + sb * 64 * PADB;

#pragma unroll
        for (int ks = 0; ks < BLK_K; ks += 16) {
            const int f0 = ks + 2 * tig;
            const int f2 = f0 + 8;
            const int o0 = ((((f0 >> 2) ^ vx) << 2) | (f0 & 3));
            const int o2 = ((((f2 >> 2) ^ vx) << 2) | (f2 & 3));

            unsigned a[2][4], b[8][2];
#pragma unroll
            for (int mt = 0; mt < 2; mt++) {
                const float* rp = stg + (warp * 32 + mt * 16 + gid) * STROW;
                float2 p0 = *reinterpret_cast<const float2*>(rp + o0);
                float2 p1 = *reinterpret_cast<const float2*>(rp + 8 * STROW + o0);
                float2 p2 = *reinterpret_cast<const float2*>(rp + o2);
                float2 p3 = *reinterpret_cast<const float2*>(rp + 8 * STROW + o2);
                nacc[mt][0] += p0.x * p0.x + p0.y * p0.y + p2.x * p2.x + p2.y * p2.y;
                nacc[mt][1] += p1.x * p1.x + p1.y * p1.y + p3.x * p3.x + p3.y * p3.y;
                __nv_bfloat162 b0 = __float22bfloat162_rn(p0);
                __nv_bfloat162 b1 = __float22bfloat162_rn(p1);
                __nv_bfloat162 b2 = __float22bfloat162_rn(p2);
                __nv_bfloat162 b3 = __float22bfloat162_rn(p3);
                a[mt][0] = *reinterpret_cast<unsigned*>(&b0);
                a[mt][1] = *reinterpret_cast<unsigned*>(&b1);
                a[mt][2] = *reinterpret_cast<unsigned*>(&b2);
                a[mt][3] = *reinterpret_cast<unsigned*>(&b3);
            }
#pragma unroll
            for (int nt = 0; nt < 8; nt++) {
                const __nv_bfloat16* bp = qb + (nt * 8 + gid) * PADB + ks + 2 * tig;
                b[nt][0] = *reinterpret_cast<const unsigned*>(bp);
                b[nt][1] = *reinterpret_cast<const unsigned*>(bp + 8);
            }
#pragma unroll
            for (int mt = 0; mt < 2; mt++)
#pragma unroll
                for (int nt = 0; nt < 8; nt++) {
                    float* c4 = acc[mt][nt];
                    asm volatile(
                        "mma.sync.aligned.m16n8k16.row.col.f32.bf16.bf16.f32 "
                        "{%0,%1,%2,%3},{%4,%5,%6,%7},{%8,%9},{%0,%1,%2,%3};"
                        : "+f"(c4[0]), "+f"(c4[1]), "+f"(c4[2]), "+f"(c4[3])
                        : "r"(a[mt][0]), "r"(a[mt][1]), "r"(a[mt][2]), "r"(a[mt][3]),
                          "r"(b[nt][0]), "r"(b[nt][1]));
                }
        }

        // ---- tile epilogue (c == NC-1): buffer 2 is free until chunk g+3 ----
        if (c == NC - 1) {
            const int tile = bid + (g / NC) * GRID;
            const int r0t  = tile * BLK_M;

            float inv_r[2][2];
#pragma unroll
            for (int mt = 0; mt < 2; mt++)
#pragma unroll
                for (int h = 0; h < 2; h++) {
                    float v = nacc[mt][h];
                    v += __shfl_xor_sync(0xffffffffu, v, 1);
                    v += __shfl_xor_sync(0xffffffffu, v, 2);
                    inv_r[mt][h] = 1.f / fmaxf(sqrtf(v), 1e-12f);
                    nacc[mt][h] = 0.f;
                }
            __syncthreads();   // all frag reads of buffer 2 done before overlay

            unsigned short* skey = reinterpret_cast<unsigned short*>(smc + SM_SKEY);

#pragma unroll
            for (int mt = 0; mt < 2; mt++) {
                const int lr0 = warp * 32 + mt * 16 + gid;
                const float inv0 = inv_r[mt][0];
                const float inv1 = inv_r[mt][1];
                const int gr0 = r0t + lr0;
#pragma unroll
                for (int nt = 0; nt < 8; nt++) {
                    const int q = nt * 8 + 2 * tig;
                    skey[q * 256 + lr0]           = (gr0 < N)     ? key16(acc[mt][nt][0] * inv0) : (unsigned short)0;
                    skey[(q + 1) * 256 + lr0]     = (gr0 < N)     ? key16(acc[mt][nt][1] * inv0) : (unsigned short)0;
                    skey[q * 256 + lr0 + 8]       = (gr0 + 8 < N) ? key16(acc[mt][nt][2] * inv1) : (unsigned short)0;
                    skey[(q + 1) * 256 + lr0 + 8] = (gr0 + 8 < N) ? key16(acc[mt][nt][3] * inv1) : (unsigned short)0;
                    acc[mt][nt][0] = acc[mt][nt][1] = acc[mt][nt][2] = acc[mt][nt][3] = 0.f;
                }
            }
            __syncthreads();

            // copy out keys (coalesced) + per-(q, tile) max via warp reduction
            const uint4* src = reinterpret_cast<const uint4*>(skey);
#pragma unroll
            for (int i = 0; i < 8; i++) {
                int idx = tid + i * 256;
                int q   = idx >> 5;      // all 32 lanes of this warp share q
                int seg = idx & 31;
                uint4 v = src[idx];
                *reinterpret_cast<uint4*>(g_key + (size_t)q * NPAD + r0t + seg * 8) = v;

                unsigned m2 = __vmaxu2(__vmaxu2(v.x, v.y), __vmaxu2(v.z, v.w));
                unsigned m = max(m2 >> 16, m2 & 0xFFFFu);
#pragma unroll
                for (int o = 16; o > 0; o >>= 1)
                    m = max(m, __shfl_xor_sync(0xffffffffu, m, o));
                if (lane == 0)
                    g_ctamax[q * NCTA_PAD + tile] = (unsigned short)m;
            }
            // next loop iteration's __syncthreads orders these skey reads
            // before issue_g(g+3) refills buffer 2.
        }
    }
}

// ---------------------------------------------------------------------------
// Kernel 3 (fused): per query — top-32 tiles, gather their keys, top-32 rows,
//   exact fp32 rescore, emit top-10. One block (256 thr) per query.
// ---------------------------------------------------------------------------
__global__ __launch_bounds__(256) void select_finalize(const float* __restrict__ db,
                                                       float* __restrict__ out,
                                                       int N, int Bq, int NCTA) {
    __shared__ unsigned w_key[8 * K_CAND];
    __shared__ int      w_row[8 * K_CAND];
    __shared__ int      selcta[K_CAND];
    __shared__ float    qsh[DIM];
    __shared__ int      cid[K_CAND];
    __shared__ float    cex[K_CAND];

    const int q    = blockIdx.x;
    const int tid  = threadIdx.x;
    const int lane = tid & 31;
    const int wid  = tid >> 5;

    for (int i = tid; i < DIM; i += 256) qsh[i] = g_qn[q * DIM + i];

    // ---- phase 1: top-32 tiles by (max desc, id asc); vectorized uint4 load ----
    {
        unsigned k8[8]; int r8[8];
#pragma unroll
        for (int t = 0; t < 8; t++) { k8[t] = 0; r8[t] = 0x7fffffff; }
        uint4 v = *reinterpret_cast<const uint4*>(g_ctamax + q * NCTA_PAD + tid * 8);
        const int base = tid * 8;
        insK<8>(v.x & 0xFFFFu, base + 0, k8, r8);
        insK<8>(v.x >> 16,     base + 1, k8, r8);
        insK<8>(v.y & 0xFFFFu, base + 2, k8, r8);
        insK<8>(v.y >> 16,     base + 3, k8, r8);
        insK<8>(v.z & 0xFFFFu, base + 4, k8, r8);
        insK<8>(v.z >> 16,     base + 5, k8, r8);
        insK<8>(v.w & 0xFFFFu, base + 6, k8, r8);
        insK<8>(v.w >> 16,     base + 7, k8, r8);

        warp_top32<8>(k8, r8, w_key, w_row, wid, lane);
        __syncthreads();
        const unsigned mk = w_key[tid];
        const int      mr = w_row[tid];
        int rank = 0;
        for (int j = 0; j < 8 * K_CAND; j++)
            rank += better_pk(w_key[j], w_row[j], mk, mr) ? 1 : 0;
        if (rank < K_CAND) selcta[rank] = mr;
    }
    __syncthreads();

    // ---- phase 2: gather 32 tile key-blocks (8192 keys), top-32 rows ----
    {
        unsigned k6[6]; int r6[6];
#pragma unroll
        for (int t = 0; t < 6; t++) { k6[t] = 0; r6[t] = 0x7fffffff; }
#pragma unroll
        for (int rep = 0; rep < 4; rep++) {
            const int slot = (tid >> 5) + rep * 8;
            const int u4   = tid & 31;
            const int cta  = selcta[slot];
            if (cta >= 0 && cta < NCTA) {
                const int rowb = cta * 256 + u4 * 8;
                uint4 v = *reinterpret_cast<const uint4*>(g_key + (size_t)q * NPAD + rowb);
                unsigned m2 = __vmaxu2(__vmaxu2(v.x, v.y), __vmaxu2(v.z, v.w));
                unsigned hm = max(m2 >> 16, m2 & 0xFFFFu);
                if (hm > k6[5]) {
                    insK<6>(v.x & 0xFFFFu, rowb + 0, k6, r6);
                    insK<6>(v.x >> 16,     rowb + 1, k6, r6);
                    insK<6>(v.y & 0xFFFFu, rowb + 2, k6, r6);
                    insK<6>(v.y >> 16,     rowb + 3, k6, r6);
                    insK<6>(v.z & 0xFFFFu, rowb + 4, k6, r6);
                    insK<6>(v.z >> 16,     rowb + 5, k6, r6);
                    insK<6>(v.w & 0xFFFFu, rowb + 6, k6, r6);
                    insK<6>(v.w >> 16,     rowb + 7, k6, r6);
                }
            }
        }
        __syncthreads();   // selcta reads done before w_key reuse
        warp_top32<6>(k6, r6, w_key, w_row, wid, lane);
        __syncthreads();
        const unsigned mk = w_key[tid];
        const int      mr = w_row[tid];
        int rank = 0;
        for (int j = 0; j < 8 * K_CAND; j++)
            rank += better_pk(w_key[j], w_row[j], mk, mr) ? 1 : 0;
        if (rank < K_CAND) cid[rank] = mr;
    }
    __syncthreads();

    // ---- phase 3: exact fp32 rescore + final top-10 ----
    for (int cc = wid; cc < K_CAND; cc += 8) {
        const int idx = cid[cc];
        float dot = 0.f, nn = 0.f;
        if (idx >= 0 && idx < N) {
            const float* row = db + (size_t)idx * DIM;
            for (int i = lane; i < DIM; i += 32) {
                float d = row[i];
                dot += qsh[i] * d;
                nn  += d * d;
            }
        }
#pragma unroll
        for (int o = 16; o > 0; o >>= 1) {
            dot += __shfl_xor_sync(0xffffffff, dot, o);
            nn  += __shfl_xor_sync(0xffffffff, nn, o);
        }
        if (lane == 0)
            cex[cc] = (idx >= 0 && idx < N)
                          ? dot / fmaxf(sqrtf(nn), 1e-12f)
                          : -FLT_MAX;
    }
    __syncthreads();

    if (tid < K_CAND) {
        const float mv = cex[tid];
        const int   mi = cid[tid];
        int rank = 0;
        for (int j = 0; j < K_CAND; j++)
            rank += better_f(cex[j], cid[j], mv, mi) ? 1 : 0;
        if (rank < TOPK) {
            out[q * TOPK + rank]             = mv;
            out[Bq * TOPK + q * TOPK + rank] = (float)mi;
        }
    }
}

// ---------------------------------------------------------------------------
extern "C" void kernel_launch(void* const* d_in, const int* in_sizes, int n_in,
                              void* d_out, int out_size) {
    const float* query = (const float*)d_in[0];
    const float* db    = (const float*)d_in[1];

    int Bq = in_sizes[0] / DIM;
    int N  = in_sizes[1] / DIM;
    if (Bq > B_Q) Bq = B_Q;
    if (N > N_MAX) N = N_MAX;

    float* out = (float*)d_out;

    static bool attr_set = false;
    if (!attr_set) {
        cudaFuncSetAttribute(gemm_tc, cudaFuncAttributeMaxDynamicSharedMemorySize,
                             SM_TOTAL);
        attr_set = true;
    }

    const int ntile = (N + BLK_M - 1) / BLK_M;   // 1954
    const int gemm_grid = 152;                   // persistent: 1 CTA/SM

    normalize_q<<<Bq, 256>>>(query);                       // 0
    gemm_tc<<<gemm_grid, 256, SM_TOTAL>>>(db, N, ntile);   // 1
    select_finalize<<<Bq, 256>>>(db, out, N, Bq, ntile);   // 2
    (void)n_in; (void)out_size;
}